// round 1
// baseline (speedup 1.0000x reference)
#include <cuda_runtime.h>
#include <math.h>

#define Bb 4
#define Tt 12
#define NN 2000
#define KK 8
#define KMAX 16
#define CC 32
#define TOT (Bb*Tt*NN)

// scratch (no allocations allowed)
__device__ int   g_nidx[2][NN][KMAX];
__device__ float g_nw[2][NN][KMAX];
__device__ int   g_M[2][NN];    // stored entries (<=KMAX)
__device__ int   g_cnt[2][NN];  // true kept count (for deg-count / log1p)
__device__ float g_deg[2][NN];  // sum of kept weights
__device__ float g_h1[(size_t)TOT * CC];

__device__ __forceinline__ float maskf(float v) {
    if (isnan(v)) v = 6.0f;
    if (isinf(v)) v = 0.0f;
    return fminf(v, 6.0f);
}

// ---------------- top-K (stable, tie-exact) ----------------
// one block per (matrix,row). Iterative argmax x8 with jax.lax.top_k tie-break
// (value desc, index asc), then collect ==thr ties for exact deg/mean semantics.
__global__ void topk_kernel(const float* __restrict__ adj,
                            const float* __restrict__ adjm) {
    int bi = blockIdx.x;
    int mat = bi / NN;
    int row = bi - mat * NN;
    const float* src = (mat == 0 ? adj : adjm) + (size_t)row * NN;

    __shared__ float sv[NN];
    __shared__ float rv[256];
    __shared__ int   ri[256];
    __shared__ float topv[KK];
    __shared__ int   topi[KK];
    __shared__ int   s_cnt;

    int tid = threadIdx.x;
    for (int i = tid; i < NN; i += 256) sv[i] = src[i];
    __syncthreads();

    for (int k = 0; k < KK; k++) {
        float bv = -INFINITY; int bidx = NN;
        for (int i = tid; i < NN; i += 256) {
            float v = sv[i];
            if (v > bv || (v == bv && i < bidx)) { bv = v; bidx = i; }
        }
        rv[tid] = bv; ri[tid] = bidx;
        __syncthreads();
        for (int s = 128; s > 0; s >>= 1) {
            if (tid < s) {
                float ov = rv[tid + s]; int oi = ri[tid + s];
                if (ov > rv[tid] || (ov == rv[tid] && oi < ri[tid])) {
                    rv[tid] = ov; ri[tid] = oi;
                }
            }
            __syncthreads();
        }
        if (tid == 0) {
            topv[k] = rv[0]; topi[k] = ri[0];
            sv[ri[0]] = -INFINITY;
            s_cnt = 0;
        }
        __syncthreads();
    }

    float thr = topv[KK - 1];
    // remaining entries >= thr are exactly == thr (ties kept by sparsify)
    for (int i = tid; i < NN; i += 256) {
        if (sv[i] >= thr) {
            int p = atomicAdd(&s_cnt, 1);
            if (p < KMAX - KK) {
                g_nidx[mat][row][KK + p] = i;
                g_nw[mat][row][KK + p]   = sv[i];
            }
        }
    }
    __syncthreads();
    if (tid == 0) {
        int extra = s_cnt;
        float deg = (float)extra * thr;
        for (int j = 0; j < KK; j++) {
            deg += topv[j];
            g_nidx[mat][row][j] = topi[j];
            g_nw[mat][row][j]   = topv[j];
        }
        int total = KK + extra;
        g_cnt[mat][row] = total;
        g_M[mat][row]   = total < KMAX ? total : KMAX;
        g_deg[mat][row] = deg;
    }
}

// ---------------- stage 1: stower0 (masking) + tcn0 ----------------
// warp per node, lane = channel. Gather C=1 scalars via lane-parallel reduce.
__global__ void stage1_kernel(const float* __restrict__ X,
                              const float* __restrict__ Theta0,
                              const float* __restrict__ bias0,
                              const float* __restrict__ Wt0,
                              const float* __restrict__ bt0) {
    __shared__ float sT0[4 * CC];
    __shared__ float sb0[CC];
    __shared__ float sWt[CC * CC];  // transposed: sWt[cp*CC+o] = Wt0[o*CC+cp]
    __shared__ float sbt[CC];
    int tid = threadIdx.x;
    for (int i = tid; i < 4 * CC; i += blockDim.x) sT0[i] = Theta0[i];
    for (int i = tid; i < CC * CC; i += blockDim.x) {
        int o = i / CC, cp = i % CC;
        sWt[cp * CC + o] = Wt0[i];
    }
    if (tid < CC) { sb0[tid] = bias0[tid]; sbt[tid] = bt0[tid]; }
    __syncthreads();

    int lane = tid & 31;
    int warp = (blockIdx.x * blockDim.x + tid) >> 5;
    int wstride = (gridDim.x * blockDim.x) >> 5;

    for (int g = warp; g < TOT; g += wstride) {
        int n  = g % NN;
        int bt = g / NN;
        int base = bt * NN;
        int M = g_M[1][n];
        float deg = g_deg[1][n];

        float w = 0.f, xv = 0.f;
        bool act = lane < M;
        if (act) {
            w = g_nw[1][n][lane];
            int mi = g_nidx[1][n][lane];
            xv = X[base + mi];
        }
        float sw  = act ? w * xv : 0.f;
        float sw2 = act ? w * xv * xv : 0.f;
        bool vld = act && (lane < KK) && (w > 0.f);
        float mx = vld ? xv : -INFINITY;
        float mn = vld ? xv : INFINITY;
        #pragma unroll
        for (int off = 16; off > 0; off >>= 1) {
            sw  += __shfl_xor_sync(0xffffffffu, sw,  off);
            sw2 += __shfl_xor_sync(0xffffffffu, sw2, off);
            mx = fmaxf(mx, __shfl_xor_sync(0xffffffffu, mx, off));
            mn = fminf(mn, __shfl_xor_sync(0xffffffffu, mn, off));
        }
        float mean = sw / deg;
        float msq  = sw2 / deg;
        float sd   = sqrtf(fmaxf(msq - mean * mean, 0.f) + 1e-5f);
        mean = maskf(mean); mx = maskf(mx); mn = maskf(mn); sd = maskf(sd);

        float o = sb0[lane]
                + mean * sT0[lane]
                + mx   * sT0[CC + lane]
                + mn   * sT0[2 * CC + lane]
                + sd   * sT0[3 * CC + lane];

        float acc = sbt[lane] + o;
        #pragma unroll
        for (int cp = 0; cp < CC; cp++)
            acc += sWt[cp * CC + lane] * __shfl_sync(0xffffffffu, o, cp);

        g_h1[(size_t)g * CC + lane] = tanhf(acc);
    }
}

// ---------------- stage 2: stower1 (scalers, Te-folded) + tcn1 + head ----------------
__global__ void stage2_kernel(const float* __restrict__ Theta1,
                              const float* __restrict__ bias1,
                              const float* __restrict__ Wt1,
                              const float* __restrict__ bt1,
                              const float* __restrict__ Wout,
                              const float* __restrict__ bout,
                              float* __restrict__ out) {
    __shared__ float sTe[4 * CC * CC];  // effective Theta for s = log1p(8): 128x32
    __shared__ float sWt[CC * CC];      // transposed Wt1
    __shared__ float sb1[CC], sbt[CC], sWo[CC];
    int tid = threadIdx.x;
    const float s8  = log1pf(8.0f);
    const float is8 = 1.0f / s8;
    for (int i = tid; i < 4 * CC * CC; i += blockDim.x)
        sTe[i] = Theta1[i] + s8 * Theta1[4 * CC * CC + i] + is8 * Theta1[8 * CC * CC + i];
    for (int i = tid; i < CC * CC; i += blockDim.x) {
        int o = i / CC, cp = i % CC;
        sWt[cp * CC + o] = Wt1[i];
    }
    if (tid < CC) { sb1[tid] = bias1[tid]; sbt[tid] = bt1[tid]; sWo[tid] = Wout[tid]; }
    __syncthreads();

    int lane = tid & 31;
    int warp = (blockIdx.x * blockDim.x + tid) >> 5;
    int wstride = (gridDim.x * blockDim.x) >> 5;
    float b_out = bout[0];

    for (int g = warp; g < TOT; g += wstride) {
        int n  = g % NN;
        int bt = g / NN;
        size_t base = (size_t)bt * NN;
        int M = g_M[0][n];
        int cntv = g_cnt[0][n];
        float deg = g_deg[0][n];

        // preload neighbor list lane-parallel, broadcast with shuffles
        float wreg = 0.f; int ireg = 0;
        if (lane < M) { wreg = g_nw[0][n][lane]; ireg = g_nidx[0][n][lane]; }

        float sw = 0.f, sw2 = 0.f, mx = -INFINITY, mn = INFINITY;
        for (int j = 0; j < M; j++) {
            float w = __shfl_sync(0xffffffffu, wreg, j);
            int  mi = __shfl_sync(0xffffffffu, ireg, j);
            float hv = g_h1[(base + mi) * CC + lane];  // coalesced 128B per neighbor
            sw  += w * hv;
            sw2 += w * hv * hv;
            if (j < KK && w > 0.f) { mx = fmaxf(mx, hv); mn = fminf(mn, hv); }
        }
        float mean = sw / deg;
        float sd   = sqrtf(fmaxf(sw2 / deg - mean * mean, 0.f) + 1e-5f);

        float outc = sb1[lane];
        if (cntv == KK) {  // warp-uniform; common case: s == log1p(8), use folded Te
            #pragma unroll
            for (int f = 0; f < CC; f++) {
                float me  = __shfl_sync(0xffffffffu, mean, f);
                float ma  = __shfl_sync(0xffffffffu, mx,   f);
                float mi2 = __shfl_sync(0xffffffffu, mn,   f);
                float st  = __shfl_sync(0xffffffffu, sd,   f);
                outc += me  * sTe[f * CC + lane]
                      + ma  * sTe[(CC + f) * CC + lane]
                      + mi2 * sTe[(2 * CC + f) * CC + lane]
                      + st  * sTe[(3 * CC + f) * CC + lane];
            }
        } else {            // rare tie case: generic A + s*B + C/s path
            float s  = log1pf((float)cntv);
            float is = 1.0f / s;
            float A = 0.f, Bs = 0.f, Cs = 0.f;
            for (int f = 0; f < CC; f++) {
                float mv[4];
                mv[0] = __shfl_sync(0xffffffffu, mean, f);
                mv[1] = __shfl_sync(0xffffffffu, mx,   f);
                mv[2] = __shfl_sync(0xffffffffu, mn,   f);
                mv[3] = __shfl_sync(0xffffffffu, sd,   f);
                #pragma unroll
                for (int q = 0; q < 4; q++) {
                    int i = q * CC + f;
                    A  += mv[q] * Theta1[i * CC + lane];
                    Bs += mv[q] * Theta1[4 * CC * CC + i * CC + lane];
                    Cs += mv[q] * Theta1[8 * CC * CC + i * CC + lane];
                }
            }
            outc += A + s * Bs + is * Cs;
        }

        float r = fmaxf(outc, 0.f);          // relu(stower1)
        float acc = sbt[lane] + r;
        #pragma unroll
        for (int cp = 0; cp < CC; cp++)
            acc += sWt[cp * CC + lane] * __shfl_sync(0xffffffffu, r, cp);
        float u = fmaxf(tanhf(acc), 0.f);    // relu(tcn1)

        float p = sWo[lane] * u;
        #pragma unroll
        for (int off = 16; off > 0; off >>= 1)
            p += __shfl_xor_sync(0xffffffffu, p, off);
        if (lane == 0) out[g] = p + b_out;
    }
}

extern "C" void kernel_launch(void* const* d_in, const int* in_sizes, int n_in,
                              void* d_out, int out_size) {
    const float* X      = (const float*)d_in[0];
    const float* adj    = (const float*)d_in[1];
    const float* adjm   = (const float*)d_in[2];
    const float* Theta0 = (const float*)d_in[3];
    const float* bias0  = (const float*)d_in[4];
    const float* Wt0    = (const float*)d_in[5];
    const float* bt0    = (const float*)d_in[6];
    const float* Theta1 = (const float*)d_in[7];
    const float* bias1  = (const float*)d_in[8];
    const float* Wt1    = (const float*)d_in[9];
    const float* bt1    = (const float*)d_in[10];
    const float* Wout   = (const float*)d_in[11];
    const float* bout   = (const float*)d_in[12];
    float* out = (float*)d_out;

    topk_kernel<<<2 * NN, 256>>>(adj, adjm);
    stage1_kernel<<<592, 512>>>(X, Theta0, bias0, Wt0, bt0);
    stage2_kernel<<<592, 512>>>(Theta1, bias1, Wt1, bt1, Wout, bout, out);
}

// round 2
// speedup vs baseline: 1.1409x; 1.1409x over previous
#include <cuda_runtime.h>
#include <math.h>

#define Bb 4
#define Tt 12
#define NN 2000
#define KK 8
#define KMAX 16
#define CC 32
#define TOT (Bb*Tt*NN)

// scratch (no allocations allowed)
__device__ int   g_nidx[2][NN][KMAX];
__device__ float g_nw[2][NN][KMAX];
__device__ int   g_M[2][NN];    // stored entries (<=KMAX)
__device__ int   g_cnt[2][NN];  // true kept count
__device__ float g_deg[2][NN];  // sum of kept weights
__device__ float g_h1[(size_t)TOT * CC];

__device__ __forceinline__ float maskf(float v) {
    if (isnan(v)) v = 6.0f;
    if (isinf(v)) v = 0.0f;
    return fminf(v, 6.0f);
}

// ---------------- top-K: warp per row, register top-8 ----------------
// Each lane keeps a sorted top-8 (value desc, stable: strict-> insert) of its
// strided slice; 8 shuffle-argmax merge rounds reproduce jax.lax.top_k
// (value desc, index asc). Then one rescan collects ==thr ties (kept by
// sparsify but absent from top_k's max/min gather).
__global__ void __launch_bounds__(256) topk_kernel(const float* __restrict__ adj,
                                                   const float* __restrict__ adjm) {
    int gw = (blockIdx.x * blockDim.x + threadIdx.x) >> 5;
    if (gw >= 2 * NN) return;
    int mat = gw / NN;
    int row = gw - mat * NN;
    const float* src = (mat == 0 ? adj : adjm) + (size_t)row * NN;
    int lane = threadIdx.x & 31;

    float v[8]; int ix[8];
    #pragma unroll
    for (int j = 0; j < 8; j++) { v[j] = -INFINITY; ix[j] = 1 << 30; }

    const int ITERS = (NN + 31) / 32;   // 63
    #pragma unroll 4
    for (int t = 0; t < ITERS; t++) {
        int i = lane + t * 32;
        float x = (i < NN) ? src[i] : -INFINITY;
        if (x > v[7]) {
            int pos = 7;
            #pragma unroll
            for (int j = 6; j >= 0; j--) if (x > v[j]) pos = j;
            #pragma unroll
            for (int j = 7; j > 0; j--) if (j > pos) { v[j] = v[j - 1]; ix[j] = ix[j - 1]; }
            #pragma unroll
            for (int j = 0; j < 8; j++) if (j == pos) { v[j] = x; ix[j] = i; }
        }
    }

    // 8-round warp merge (value desc, index asc)
    float topv[8]; int topi[8];
    #pragma unroll
    for (int k = 0; k < 8; k++) {
        float cv = v[0]; int ci = ix[0];
        #pragma unroll
        for (int off = 16; off > 0; off >>= 1) {
            float ov = __shfl_xor_sync(0xffffffffu, cv, off);
            int   oi = __shfl_xor_sync(0xffffffffu, ci, off);
            if (ov > cv || (ov == cv && oi < ci)) { cv = ov; ci = oi; }
        }
        topv[k] = cv; topi[k] = ci;
        if (ix[0] == ci) {   // winner lane pops its head
            #pragma unroll
            for (int j = 0; j < 7; j++) { v[j] = v[j + 1]; ix[j] = ix[j + 1]; }
            v[7] = -INFINITY; ix[7] = 1 << 30;
        }
    }

    float thr = topv[7];
    // rescan: kept-but-not-in-top8 entries (exact ==thr ties)
    int extraBase = 0;
    for (int t = 0; t < ITERS; t++) {
        int i = lane + t * 32;
        bool isExtra = false;
        float x = 0.f;
        if (i < NN) {
            x = src[i];
            if (x >= thr) {
                isExtra = true;
                #pragma unroll
                for (int k = 0; k < 8; k++) if (i == topi[k]) isExtra = false;
            }
        }
        unsigned m = __ballot_sync(0xffffffffu, isExtra);
        if (isExtra) {
            int p = extraBase + __popc(m & ((1u << lane) - 1u));
            if (p < KMAX - KK) {
                g_nidx[mat][row][KK + p] = i;
                g_nw[mat][row][KK + p]   = x;
            }
        }
        extraBase += __popc(m);
    }

    if (lane == 0) {
        float deg = (float)extraBase * thr;
        #pragma unroll
        for (int k = 0; k < 8; k++) {
            deg += topv[k];
            g_nidx[mat][row][k] = topi[k];
            g_nw[mat][row][k]   = topv[k];
        }
        int total = KK + extraBase;
        g_cnt[mat][row] = total;
        g_M[mat][row]   = total < KMAX ? total : KMAX;
        g_deg[mat][row] = deg;
    }
}

// ---------------- stage 1: stower0 (masking) + tcn0 ----------------
__global__ void __launch_bounds__(512) stage1_kernel(const float* __restrict__ X,
                              const float* __restrict__ Theta0,
                              const float* __restrict__ bias0,
                              const float* __restrict__ Wt0,
                              const float* __restrict__ bt0) {
    __shared__ float sT0[4 * CC];
    __shared__ float sb0[CC];
    __shared__ float sWt[CC * CC];   // transposed: sWt[cp*CC+o] = Wt0[o*CC+cp]
    __shared__ float sbt[CC];
    __shared__ float sR[16][CC];     // per-warp tcn input staging
    int tid = threadIdx.x;
    for (int i = tid; i < 4 * CC; i += blockDim.x) sT0[i] = Theta0[i];
    for (int i = tid; i < CC * CC; i += blockDim.x) {
        int o = i / CC, cp = i % CC;
        sWt[cp * CC + o] = Wt0[i];
    }
    if (tid < CC) { sb0[tid] = bias0[tid]; sbt[tid] = bt0[tid]; }
    __syncthreads();

    int lane = tid & 31;
    int w    = tid >> 5;
    int warp = (blockIdx.x * blockDim.x + tid) >> 5;
    int wstride = (gridDim.x * blockDim.x) >> 5;

    for (int g = warp; g < TOT; g += wstride) {
        int n  = g % NN;
        int bt = g / NN;
        int base = bt * NN;
        int M = g_M[1][n];
        float deg = g_deg[1][n];

        float wt = 0.f, xv = 0.f;
        bool act = lane < M;
        if (act) {
            wt = g_nw[1][n][lane];
            int mi = g_nidx[1][n][lane];
            xv = X[base + mi];
        }
        float sw  = act ? wt * xv : 0.f;
        float sw2 = act ? wt * xv * xv : 0.f;
        bool vld = act && (lane < KK) && (wt > 0.f);
        float mx = vld ? xv : -INFINITY;
        float mn = vld ? xv : INFINITY;
        #pragma unroll
        for (int off = 16; off > 0; off >>= 1) {
            sw  += __shfl_xor_sync(0xffffffffu, sw,  off);
            sw2 += __shfl_xor_sync(0xffffffffu, sw2, off);
            mx = fmaxf(mx, __shfl_xor_sync(0xffffffffu, mx, off));
            mn = fminf(mn, __shfl_xor_sync(0xffffffffu, mn, off));
        }
        float mean = sw / deg;
        float msq  = sw2 / deg;
        float sd   = sqrtf(fmaxf(msq - mean * mean, 0.f) + 1e-5f);
        mean = maskf(mean); mx = maskf(mx); mn = maskf(mn); sd = maskf(sd);

        float o = sb0[lane]
                + mean * sT0[lane]
                + mx   * sT0[CC + lane]
                + mn   * sT0[2 * CC + lane]
                + sd   * sT0[3 * CC + lane];

        // tcn via smem staging (LDS.128 instead of shuffles)
        sR[w][lane] = o;
        __syncwarp();
        float acc = sbt[lane] + o;
        const float4* r4 = (const float4*)&sR[w][0];
        #pragma unroll
        for (int q = 0; q < 8; q++) {
            float4 r = r4[q];
            acc += sWt[(4 * q + 0) * CC + lane] * r.x
                 + sWt[(4 * q + 1) * CC + lane] * r.y
                 + sWt[(4 * q + 2) * CC + lane] * r.z
                 + sWt[(4 * q + 3) * CC + lane] * r.w;
        }
        __syncwarp();
        g_h1[(size_t)g * CC + lane] = tanhf(acc);
    }
}

// ---------------- stage 2: stower1 (scalers folded) + tcn1 + head ----------------
__global__ void __launch_bounds__(512) stage2_kernel(const float* __restrict__ Theta1,
                              const float* __restrict__ bias1,
                              const float* __restrict__ Wt1,
                              const float* __restrict__ bt1,
                              const float* __restrict__ Wout,
                              const float* __restrict__ bout,
                              float* __restrict__ out) {
    // sTe2[(f*4+q)*CC + o] = folded Theta for stat q, feature f, output o
    __shared__ float sTe2[4 * CC * CC];
    __shared__ float sWt[CC * CC];    // transposed Wt1
    __shared__ float sb1[CC], sbt[CC], sWo[CC];
    __shared__ float4 sS[16 * CC];    // per-warp stats: [w*32+f] = (mean,mx,mn,sd)
    __shared__ float sR[16][CC];
    int tid = threadIdx.x;
    const float s8  = log1pf(8.0f);
    const float is8 = 1.0f / s8;
    for (int i = tid; i < 4 * CC * CC; i += blockDim.x) {
        int o = i % CC, rest = i / CC;
        int q = rest % 4, f = rest / 4;
        int src = (q * CC + f) * CC + o;
        sTe2[i] = Theta1[src] + s8 * Theta1[4 * CC * CC + src] + is8 * Theta1[8 * CC * CC + src];
    }
    for (int i = tid; i < CC * CC; i += blockDim.x) {
        int o = i / CC, cp = i % CC;
        sWt[cp * CC + o] = Wt1[i];
    }
    if (tid < CC) { sb1[tid] = bias1[tid]; sbt[tid] = bt1[tid]; sWo[tid] = Wout[tid]; }
    __syncthreads();

    int lane = tid & 31;
    int w    = tid >> 5;
    int warp = (blockIdx.x * blockDim.x + tid) >> 5;
    int wstride = (gridDim.x * blockDim.x) >> 5;
    float b_out = bout[0];

    for (int g = warp; g < TOT; g += wstride) {
        int n  = g % NN;
        int bt = g / NN;
        size_t base = (size_t)bt * NN;
        int M = g_M[0][n];
        int cntv = g_cnt[0][n];
        float deg = g_deg[0][n];

        float wreg = 0.f; int ireg = 0;
        if (lane < M) { wreg = g_nw[0][n][lane]; ireg = g_nidx[0][n][lane]; }

        float sw = 0.f, sw2 = 0.f, mx = -INFINITY, mn = INFINITY;
        for (int j = 0; j < M; j++) {
            float wt = __shfl_sync(0xffffffffu, wreg, j);
            int  mi = __shfl_sync(0xffffffffu, ireg, j);
            float hv = g_h1[(base + mi) * CC + lane];   // coalesced 128B
            sw  += wt * hv;
            sw2 += wt * hv * hv;
            if (j < KK && wt > 0.f) { mx = fmaxf(mx, hv); mn = fminf(mn, hv); }
        }
        float mean = sw / deg;
        float sd   = sqrtf(fmaxf(sw2 / deg - mean * mean, 0.f) + 1e-5f);

        float outc = sb1[lane];
        if (cntv == KK) {  // warp-uniform common case (s == log1p(8), folded Te)
            float4 my; my.x = mean; my.y = mx; my.z = mn; my.w = sd;
            sS[w * CC + lane] = my;
            __syncwarp();
            #pragma unroll
            for (int f = 0; f < CC; f++) {
                float4 st = sS[w * CC + f];
                outc += st.x * sTe2[(f * 4 + 0) * CC + lane]
                      + st.y * sTe2[(f * 4 + 1) * CC + lane]
                      + st.z * sTe2[(f * 4 + 2) * CC + lane]
                      + st.w * sTe2[(f * 4 + 3) * CC + lane];
            }
            __syncwarp();
        } else {            // rare tie case: generic A + s*B + C/s path
            float s  = log1pf((float)cntv);
            float is = 1.0f / s;
            float A = 0.f, Bs = 0.f, Cs = 0.f;
            for (int f = 0; f < CC; f++) {
                float mv[4];
                mv[0] = __shfl_sync(0xffffffffu, mean, f);
                mv[1] = __shfl_sync(0xffffffffu, mx,   f);
                mv[2] = __shfl_sync(0xffffffffu, mn,   f);
                mv[3] = __shfl_sync(0xffffffffu, sd,   f);
                #pragma unroll
                for (int q = 0; q < 4; q++) {
                    int i = q * CC + f;
                    A  += mv[q] * Theta1[i * CC + lane];
                    Bs += mv[q] * Theta1[4 * CC * CC + i * CC + lane];
                    Cs += mv[q] * Theta1[8 * CC * CC + i * CC + lane];
                }
            }
            outc += A + s * Bs + is * Cs;
        }

        float r = fmaxf(outc, 0.f);            // relu(stower1)
        sR[w][lane] = r;
        __syncwarp();
        float acc = sbt[lane] + r;
        const float4* r4 = (const float4*)&sR[w][0];
        #pragma unroll
        for (int q = 0; q < 8; q++) {
            float4 rr = r4[q];
            acc += sWt[(4 * q + 0) * CC + lane] * rr.x
                 + sWt[(4 * q + 1) * CC + lane] * rr.y
                 + sWt[(4 * q + 2) * CC + lane] * rr.z
                 + sWt[(4 * q + 3) * CC + lane] * rr.w;
        }
        __syncwarp();
        float u = fmaxf(tanhf(acc), 0.f);      // relu(tcn1)

        float p = sWo[lane] * u;
        #pragma unroll
        for (int off = 16; off > 0; off >>= 1)
            p += __shfl_xor_sync(0xffffffffu, p, off);
        if (lane == 0) out[g] = p + b_out;
    }
}

extern "C" void kernel_launch(void* const* d_in, const int* in_sizes, int n_in,
                              void* d_out, int out_size) {
    const float* X      = (const float*)d_in[0];
    const float* adj    = (const float*)d_in[1];
    const float* adjm   = (const float*)d_in[2];
    const float* Theta0 = (const float*)d_in[3];
    const float* bias0  = (const float*)d_in[4];
    const float* Wt0    = (const float*)d_in[5];
    const float* bt0    = (const float*)d_in[6];
    const float* Theta1 = (const float*)d_in[7];
    const float* bias1  = (const float*)d_in[8];
    const float* Wt1    = (const float*)d_in[9];
    const float* bt1    = (const float*)d_in[10];
    const float* Wout   = (const float*)d_in[11];
    const float* bout   = (const float*)d_in[12];
    float* out = (float*)d_out;

    topk_kernel<<<(2 * NN * 32 + 255) / 256, 256>>>(adj, adjm);
    stage1_kernel<<<592, 512>>>(X, Theta0, bias0, Wt0, bt0);
    stage2_kernel<<<592, 512>>>(Theta1, bias1, Wt1, bt1, Wout, bout, out);
}

// round 3
// speedup vs baseline: 1.6117x; 1.4127x over previous
#include <cuda_runtime.h>
#include <math.h>

#define Bb 4
#define Tt 12
#define NN 2000
#define KK 8
#define KMAX 16
#define CC 32
#define TOT (Bb*Tt*NN)
#define NG (TOT/4)            // 24000 node-groups of 4

// scratch (no allocations allowed)
__device__ int   g_nidx[2][NN][KMAX];
__device__ float g_nw[2][NN][KMAX];
__device__ int   g_M[2][NN];    // stored entries (<=KMAX)
__device__ int   g_cnt[2][NN];  // true kept count
__device__ float g_deg[2][NN];  // sum of kept weights
__device__ float g_h1[(size_t)TOT * CC];

__device__ __forceinline__ float maskf(float v) {
    if (isnan(v)) v = 6.0f;
    if (isinf(v)) v = 0.0f;
    return fminf(v, 6.0f);
}

// ---------------- top-K: warp per row, values-only threshold + count pass ----
// Pass 1: per-lane SORTED top-8 values (15 FMNMX insert, no indices), then an
// 8-round warp merge gives the exact 8th-largest value thr.
// Pass 2: count/compact: entries > thr (at most 7) are top-k members; ==thr
// ties resolved by smallest index (jax.lax.top_k stable order). deg/cnt from
// counts. Kept-set order in storage: [gt entries idx-asc][eq entries idx-asc];
// first 8 stored entries == exact top_k set (order within is irrelevant
// downstream: max/min are order-invariant, mean uses all kept).
__global__ void __launch_bounds__(128) topk_kernel(const float* __restrict__ adj,
                                                   const float* __restrict__ adjm) {
    int gw = (blockIdx.x * 128 + threadIdx.x) >> 5;
    if (gw >= 2 * NN) return;
    int mat = gw / NN;
    int row = gw - mat * NN;
    const float* src = (mat == 0 ? adj : adjm) + (size_t)row * NN;
    const float4* src4 = (const float4*)src;   // NN=2000 -> 500 float4
    int lane = threadIdx.x & 31;
    unsigned lt = (1u << lane) - 1u;

    float v0=-INFINITY,v1=-INFINITY,v2=-INFINITY,v3=-INFINITY,
          v4=-INFINITY,v5=-INFINITY,v6=-INFINITY,v7=-INFINITY;

    #define INS(xx) do { float x_ = (xx); if (x_ > v7) { \
        v7 = fmaxf(v7, fminf(v6, x_)); \
        v6 = fmaxf(v6, fminf(v5, x_)); \
        v5 = fmaxf(v5, fminf(v4, x_)); \
        v4 = fmaxf(v4, fminf(v3, x_)); \
        v3 = fmaxf(v3, fminf(v2, x_)); \
        v2 = fmaxf(v2, fminf(v1, x_)); \
        v1 = fmaxf(v1, fminf(v0, x_)); \
        v0 = fmaxf(v0, x_); } } while(0)

    #pragma unroll 4
    for (int t = 0; t < 16; t++) {
        int i4 = lane + t * 32;
        if (i4 < 500) {
            float4 f = src4[i4];
            INS(f.x); INS(f.y); INS(f.z); INS(f.w);
        }
    }
    #undef INS

    // 8-round warp merge on sorted lists -> exact 8th largest
    float thr = -INFINITY;
    #pragma unroll
    for (int k = 0; k < 8; k++) {
        float cv = v0; int cl = lane;
        #pragma unroll
        for (int off = 16; off > 0; off >>= 1) {
            float ov = __shfl_xor_sync(0xffffffffu, cv, off);
            int   ol = __shfl_xor_sync(0xffffffffu, cl, off);
            if (ov > cv || (ov == cv && ol < cl)) { cv = ov; cl = ol; }
        }
        if (cl == lane) {  // winning lane pops its head
            v0=v1; v1=v2; v2=v3; v3=v4; v4=v5; v5=v6; v6=v7; v7=-INFINITY;
        }
        thr = cv;
    }

    // Pass 2: compact >thr (slots [0..cgt)), ==thr (slots [8..8+min(ceq,8)))
    int cgt = 0, ceq = 0;
    float sgt = 0.f;
    #pragma unroll 2
    for (int t = 0; t < 16; t++) {
        int i4 = lane + t * 32;
        float4 f;
        if (i4 < 500) f = src4[i4];
        else { f.x=f.y=f.z=f.w=-INFINITY; }
        int ib = 4 * i4;
        #pragma unroll
        for (int s = 0; s < 4; s++) {
            float x = (s==0)?f.x:(s==1)?f.y:(s==2)?f.z:f.w;
            int   i = ib + s;
            bool gt = x >  thr;
            bool ge = x >= thr;
            unsigned mgt = __ballot_sync(0xffffffffu, gt);
            unsigned mge = __ballot_sync(0xffffffffu, ge);
            unsigned meq = mge & ~mgt;
            if (gt) {
                int p = cgt + __popc(mgt & lt);   // cgt <= 7 always
                g_nidx[mat][row][p] = i;
                g_nw[mat][row][p]   = x;
                sgt += x;
            }
            cgt += __popc(mgt);
            if (meq) {
                if (ge && !gt) {
                    int p = ceq + __popc(meq & lt);
                    if (p < 8) {
                        g_nidx[mat][row][8 + p] = i;
                        g_nw[mat][row][8 + p]   = x;
                    }
                }
                ceq += __popc(meq);
            }
        }
    }
    #pragma unroll
    for (int off = 16; off > 0; off >>= 1)
        sgt += __shfl_xor_sync(0xffffffffu, sgt, off);

    if (lane == 0) {
        int cnt = cgt + ceq;
        int eq_stored = ceq < 8 ? ceq : 8;
        int M = cgt + eq_stored;          // <= 15
        // shift eq entries down to [cgt..): dst < src, safe in order
        for (int e = 0; e < eq_stored; e++) {
            g_nidx[mat][row][cgt + e] = g_nidx[mat][row][8 + e];
            g_nw[mat][row][cgt + e]   = g_nw[mat][row][8 + e];
        }
        g_M[mat][row]   = M;
        g_cnt[mat][row] = cnt;
        g_deg[mat][row] = sgt + (float)ceq * thr;
    }
}

// ---------------- stage 1: stower0 (masking) + tcn0, 4 nodes per warp -------
__global__ void __launch_bounds__(256) stage1_kernel(const float* __restrict__ X,
                              const float* __restrict__ Theta0,
                              const float* __restrict__ bias0,
                              const float* __restrict__ Wt0,
                              const float* __restrict__ bt0) {
    __shared__ float sT0[4 * CC];
    __shared__ float sb0[CC];
    __shared__ float sWt[CC * CC];     // transposed: sWt[cp*CC+o] = Wt0[o*CC+cp]
    __shared__ float sbt[CC];
    __shared__ float sR[8][4][CC];     // per-warp per-node tcn staging
    int tid = threadIdx.x;
    for (int i = tid; i < 4 * CC; i += 256) sT0[i] = Theta0[i];
    for (int i = tid; i < CC * CC; i += 256) {
        int o = i / CC, cp = i % CC;
        sWt[cp * CC + o] = Wt0[i];
    }
    if (tid < CC) { sb0[tid] = bias0[tid]; sbt[tid] = bt0[tid]; }
    __syncthreads();

    int lane = tid & 31;
    int w    = tid >> 5;
    int wg = blockIdx.x * 8 + w;
    if (wg >= NG) return;
    int g0 = wg * 4;

    float o_u[4];
    #pragma unroll
    for (int u = 0; u < 4; u++) {
        int g = g0 + u;
        int n  = g % NN;
        int bt = g / NN;
        int base = bt * NN;
        int M = g_M[1][n];
        float deg = g_deg[1][n];

        float wt = 0.f, xv = 0.f;
        bool act = lane < M;
        if (act) {
            wt = g_nw[1][n][lane];
            xv = X[base + g_nidx[1][n][lane]];
        }
        float sw  = act ? wt * xv : 0.f;
        float sw2 = act ? wt * xv * xv : 0.f;
        bool vld = act && (lane < KK) && (wt > 0.f);
        float mx = vld ? xv : -INFINITY;
        float mn = vld ? xv : INFINITY;
        #pragma unroll
        for (int off = 16; off > 0; off >>= 1) {
            sw  += __shfl_xor_sync(0xffffffffu, sw,  off);
            sw2 += __shfl_xor_sync(0xffffffffu, sw2, off);
            mx = fmaxf(mx, __shfl_xor_sync(0xffffffffu, mx, off));
            mn = fminf(mn, __shfl_xor_sync(0xffffffffu, mn, off));
        }
        float mean = sw / deg;
        float sd   = sqrtf(fmaxf(sw2 / deg - mean * mean, 0.f) + 1e-5f);
        mean = maskf(mean); mx = maskf(mx); mn = maskf(mn); sd = maskf(sd);

        o_u[u] = sb0[lane]
               + mean * sT0[lane]
               + mx   * sT0[CC + lane]
               + mn   * sT0[2 * CC + lane]
               + sd   * sT0[3 * CC + lane];
        sR[w][u][lane] = o_u[u];
    }
    __syncwarp();

    float acc[4];
    #pragma unroll
    for (int u = 0; u < 4; u++) acc[u] = sbt[lane] + o_u[u];
    #pragma unroll
    for (int q = 0; q < 8; q++) {
        float w0 = sWt[(4 * q + 0) * CC + lane];
        float w1 = sWt[(4 * q + 1) * CC + lane];
        float w2 = sWt[(4 * q + 2) * CC + lane];
        float w3 = sWt[(4 * q + 3) * CC + lane];
        #pragma unroll
        for (int u = 0; u < 4; u++) {
            float4 r = ((const float4*)&sR[w][u][0])[q];
            acc[u] += w0 * r.x + w1 * r.y + w2 * r.z + w3 * r.w;
        }
    }
    #pragma unroll
    for (int u = 0; u < 4; u++)
        g_h1[(size_t)(g0 + u) * CC + lane] = tanhf(acc[u]);
}

// ---------------- stage 2: stower1 (scalers folded) + tcn1 + head, 4/warp ---
__global__ void __launch_bounds__(256) stage2_kernel(const float* __restrict__ Theta1,
                              const float* __restrict__ bias1,
                              const float* __restrict__ Wt1,
                              const float* __restrict__ bt1,
                              const float* __restrict__ Wout,
                              const float* __restrict__ bout,
                              float* __restrict__ out) {
    // sTe2[(f*4+q)*CC + o] = folded Theta for stat q, feature f, output o
    __shared__ float sTe2[4 * CC * CC];
    __shared__ float sWt[CC * CC];     // transposed Wt1
    __shared__ float sb1[CC], sbt[CC], sWo[CC];
    __shared__ float4 sS[8][4][CC];    // per-warp per-node stats (reused for tcn staging)
    int tid = threadIdx.x;
    const float s8  = log1pf(8.0f);
    const float is8 = 1.0f / s8;
    for (int i = tid; i < 4 * CC * CC; i += 256) {
        int o = i % CC, rest = i / CC;
        int q = rest % 4, f = rest / 4;
        int src = (q * CC + f) * CC + o;
        sTe2[i] = Theta1[src] + s8 * Theta1[4 * CC * CC + src] + is8 * Theta1[8 * CC * CC + src];
    }
    for (int i = tid; i < CC * CC; i += 256) {
        int o = i / CC, cp = i % CC;
        sWt[cp * CC + o] = Wt1[i];
    }
    if (tid < CC) { sb1[tid] = bias1[tid]; sbt[tid] = bt1[tid]; sWo[tid] = Wout[tid]; }
    __syncthreads();

    int lane = tid & 31;
    int w    = tid >> 5;
    int wg = blockIdx.x * 8 + w;
    if (wg >= NG) return;
    int g0 = wg * 4;
    float b_out = bout[0];

    // Phase A: gather + stats for 4 nodes
    int cntOK = 1;
    #pragma unroll
    for (int u = 0; u < 4; u++) {
        int g = g0 + u;
        int n  = g % NN;
        int bt = g / NN;
        size_t base = (size_t)bt * NN;
        int M = g_M[0][n];
        int cv = g_cnt[0][n];
        float deg = g_deg[0][n];
        cntOK &= (cv == KK);

        float wreg = 0.f; int ireg = 0;
        if (lane < M) { wreg = g_nw[0][n][lane]; ireg = g_nidx[0][n][lane]; }

        float sw = 0.f, sw2 = 0.f, mx = -INFINITY, mn = INFINITY;
        for (int j = 0; j < M; j++) {
            float wt = __shfl_sync(0xffffffffu, wreg, j);
            int  mi = __shfl_sync(0xffffffffu, ireg, j);
            float hv = g_h1[(base + mi) * CC + lane];
            sw  += wt * hv;
            sw2 += wt * hv * hv;
            if (j < KK && wt > 0.f) { mx = fmaxf(mx, hv); mn = fminf(mn, hv); }
        }
        float mean = sw / deg;
        float sd   = sqrtf(fmaxf(sw2 / deg - mean * mean, 0.f) + 1e-5f);
        float4 st; st.x = mean; st.y = mx; st.z = mn; st.w = sd;
        sS[w][u][lane] = st;
    }
    __syncwarp();

    // Phase B: Theta1 matmul
    float acc[4];
    #pragma unroll
    for (int u = 0; u < 4; u++) acc[u] = sb1[lane];

    if (cntOK) {   // common case: s == log1p(8) -> folded Te, weights amortized x4
        #pragma unroll
        for (int f = 0; f < CC; f++) {
            float w0 = sTe2[(f * 4 + 0) * CC + lane];
            float w1 = sTe2[(f * 4 + 1) * CC + lane];
            float w2 = sTe2[(f * 4 + 2) * CC + lane];
            float w3 = sTe2[(f * 4 + 3) * CC + lane];
            #pragma unroll
            for (int u = 0; u < 4; u++) {
                float4 st = sS[w][u][f];
                acc[u] += st.x * w0 + st.y * w1 + st.z * w2 + st.w * w3;
            }
        }
    } else {       // rare tie case: generic A + s*B + C/s from global Theta1
        #pragma unroll
        for (int u = 0; u < 4; u++) {
            int g = g0 + u;
            int n = g % NN;
            float s  = log1pf((float)g_cnt[0][n]);
            float is = 1.0f / s;
            float A = 0.f, Bs = 0.f, Cs = 0.f;
            for (int f = 0; f < CC; f++) {
                float4 st = sS[w][u][f];
                float mv[4] = {st.x, st.y, st.z, st.w};
                #pragma unroll
                for (int q = 0; q < 4; q++) {
                    int i = q * CC + f;
                    A  += mv[q] * Theta1[i * CC + lane];
                    Bs += mv[q] * Theta1[4 * CC * CC + i * CC + lane];
                    Cs += mv[q] * Theta1[8 * CC * CC + i * CC + lane];
                }
            }
            acc[u] += A + s * Bs + is * Cs;
        }
    }

    // Phase C: relu -> tcn1 (reuse sS storage for r staging) -> head
    float r_u[4];
    #pragma unroll
    for (int u = 0; u < 4; u++) r_u[u] = fmaxf(acc[u], 0.f);
    __syncwarp();
    #pragma unroll
    for (int u = 0; u < 4; u++)
        ((float*)&sS[w][u][0])[lane] = r_u[u];
    __syncwarp();

    float acc2[4];
    #pragma unroll
    for (int u = 0; u < 4; u++) acc2[u] = sbt[lane] + r_u[u];
    #pragma unroll
    for (int q = 0; q < 8; q++) {
        float w0 = sWt[(4 * q + 0) * CC + lane];
        float w1 = sWt[(4 * q + 1) * CC + lane];
        float w2 = sWt[(4 * q + 2) * CC + lane];
        float w3 = sWt[(4 * q + 3) * CC + lane];
        #pragma unroll
        for (int u = 0; u < 4; u++) {
            float4 rr = ((const float4*)&sS[w][u][0])[q];
            acc2[u] += w0 * rr.x + w1 * rr.y + w2 * rr.z + w3 * rr.w;
        }
    }

    #pragma unroll
    for (int u = 0; u < 4; u++) {
        float uu = fmaxf(tanhf(acc2[u]), 0.f);
        float p = sWo[lane] * uu;
        #pragma unroll
        for (int off = 16; off > 0; off >>= 1)
            p += __shfl_xor_sync(0xffffffffu, p, off);
        if (lane == 0) out[g0 + u] = p + b_out;
    }
}

extern "C" void kernel_launch(void* const* d_in, const int* in_sizes, int n_in,
                              void* d_out, int out_size) {
    const float* X      = (const float*)d_in[0];
    const float* adj    = (const float*)d_in[1];
    const float* adjm   = (const float*)d_in[2];
    const float* Theta0 = (const float*)d_in[3];
    const float* bias0  = (const float*)d_in[4];
    const float* Wt0    = (const float*)d_in[5];
    const float* bt0    = (const float*)d_in[6];
    const float* Theta1 = (const float*)d_in[7];
    const float* bias1  = (const float*)d_in[8];
    const float* Wt1    = (const float*)d_in[9];
    const float* bt1    = (const float*)d_in[10];
    const float* Wout   = (const float*)d_in[11];
    const float* bout   = (const float*)d_in[12];
    float* out = (float*)d_out;

    topk_kernel<<<(2 * NN * 32 + 127) / 128, 128>>>(adj, adjm);
    stage1_kernel<<<(NG + 7) / 8, 256>>>(X, Theta0, bias0, Wt0, bt0);
    stage2_kernel<<<(NG + 7) / 8, 256>>>(Theta1, bias1, Wt1, bt1, Wout, bout, out);
}

// round 4
// speedup vs baseline: 1.8822x; 1.1678x over previous
#include <cuda_runtime.h>
#include <math.h>

#define Bb 4
#define Tt 12
#define NN 2000
#define KK 8
#define KMAX 16
#define CC 32
#define TOT (Bb*Tt*NN)
#define UU 4
#define NG (TOT/UU)          // 24000 groups of 4 nodes

// ---- scratch (no allocations allowed) ----
__device__ float2 g_nwi[2][NN][KMAX];  // (weight, idx-as-bits)
__device__ int    g_M[2][NN];          // stored entries (<=15)
__device__ int    g_cnt[2][NN];        // true kept count
__device__ float  g_inv[2][NN];        // 1/deg
__device__ float  g_h1[(size_t)TOT * CC];
__device__ float4 g_Te3[CC * CC];      // folded Theta1: [f*32+o] = {q=0..3}

__device__ __forceinline__ float maskf(float v) {
    if (isnan(v)) v = 6.0f;
    if (isinf(v)) v = 0.0f;
    return fminf(v, 6.0f);
}

__device__ __forceinline__ float ftanh(float x) {
    float e = __expf(2.0f * x);
    return 1.0f - __fdividef(2.0f, e + 1.0f);
}

// ---------------- top-K: warp per row ----------------
// Pass 1: per-lane sorted top-8 values (branchless 15 FMNMX), 8-round warp
// merge -> exact 8th-largest thr. Pass 2 (any-guarded): compact >thr entries
// (idx asc) then ==thr ties (idx asc) -> first 8 stored == exact top_k set.
__global__ void __launch_bounds__(256) topk_kernel(const float* __restrict__ adj,
                                                   const float* __restrict__ adjm) {
    int gw = (blockIdx.x * 256 + threadIdx.x) >> 5;
    if (gw >= 2 * NN) return;
    int mat = gw / NN;
    int row = gw - mat * NN;
    const float4* src4 = (const float4*)((mat == 0 ? adj : adjm) + (size_t)row * NN);
    int lane = threadIdx.x & 31;
    unsigned lt = (1u << lane) - 1u;

    float v0=-INFINITY,v1=-INFINITY,v2=-INFINITY,v3=-INFINITY,
          v4=-INFINITY,v5=-INFINITY,v6=-INFINITY,v7=-INFINITY;

    #define INS(xx) do { float x_ = (xx); \
        v7 = fmaxf(v7, fminf(v6, x_)); \
        v6 = fmaxf(v6, fminf(v5, x_)); \
        v5 = fmaxf(v5, fminf(v4, x_)); \
        v4 = fmaxf(v4, fminf(v3, x_)); \
        v3 = fmaxf(v3, fminf(v2, x_)); \
        v2 = fmaxf(v2, fminf(v1, x_)); \
        v1 = fmaxf(v1, fminf(v0, x_)); \
        v0 = fmaxf(v0, x_); } while(0)

    #pragma unroll 4
    for (int t = 0; t < 16; t++) {
        int i4 = lane + t * 32;
        if (i4 < 500) {
            float4 f = __ldg(&src4[i4]);
            INS(f.x); INS(f.y); INS(f.z); INS(f.w);
        }
    }
    #undef INS

    float thr = -INFINITY;
    #pragma unroll
    for (int k = 0; k < 8; k++) {
        float cv = v0; int cl = lane;
        #pragma unroll
        for (int off = 16; off > 0; off >>= 1) {
            float ov = __shfl_xor_sync(0xffffffffu, cv, off);
            int   ol = __shfl_xor_sync(0xffffffffu, cl, off);
            if (ov > cv || (ov == cv && ol < cl)) { cv = ov; cl = ol; }
        }
        if (cl == lane) { v0=v1; v1=v2; v2=v3; v3=v4; v4=v5; v5=v6; v6=v7; v7=-INFINITY; }
        thr = cv;
    }

    // Pass 2 with per-group any-guard
    int cgt = 0, ceq = 0;
    float sgt = 0.f;
    for (int t = 0; t < 16; t++) {
        int i4 = lane + t * 32;
        float4 f;
        if (i4 < 500) f = __ldg(&src4[i4]);
        else { f.x=f.y=f.z=f.w=-INFINITY; }
        bool any = (f.x >= thr) | (f.y >= thr) | (f.z >= thr) | (f.w >= thr);
        if (__ballot_sync(0xffffffffu, any) == 0u) continue;
        int ib = 4 * i4;
        #pragma unroll
        for (int s = 0; s < 4; s++) {
            float x = (s==0)?f.x:(s==1)?f.y:(s==2)?f.z:f.w;
            int   i = ib + s;
            bool gt = x >  thr;
            bool ge = x >= thr;
            unsigned mgt = __ballot_sync(0xffffffffu, gt);
            unsigned mge = __ballot_sync(0xffffffffu, ge);
            unsigned meq = mge & ~mgt;
            if (gt) {
                int p = cgt + __popc(mgt & lt);   // cgt <= 7 always
                g_nwi[mat][row][p] = make_float2(x, __int_as_float(i));
                sgt += x;
            }
            cgt += __popc(mgt);
            if (meq) {
                if (ge && !gt) {
                    int p = ceq + __popc(meq & lt);
                    if (p < 8) g_nwi[mat][row][8 + p] = make_float2(x, __int_as_float(i));
                }
                ceq += __popc(meq);
            }
        }
    }
    #pragma unroll
    for (int off = 16; off > 0; off >>= 1)
        sgt += __shfl_xor_sync(0xffffffffu, sgt, off);

    if (lane == 0) {
        int cnt = cgt + ceq;
        int eq_stored = ceq < 8 ? ceq : 8;
        int M = cgt + eq_stored;           // >= 8, <= 15
        for (int e = 0; e < eq_stored; e++)         // shift eq down (dst<src)
            g_nwi[mat][row][cgt + e] = g_nwi[mat][row][8 + e];
        g_M[mat][row]   = M;
        g_cnt[mat][row] = cnt;
        g_inv[mat][row] = 1.0f / (sgt + (float)ceq * thr);
    }
}

// ---------------- prep: fold Theta1 into float4 layout ----------------
__global__ void __launch_bounds__(256) prep_kernel(const float* __restrict__ Theta1) {
    int idx = blockIdx.x * 256 + threadIdx.x;
    if (idx >= CC * CC) return;
    int f = idx >> 5, o = idx & 31;
    const float s8  = log1pf(8.0f);
    const float is8 = 1.0f / s8;
    float4 v;
    float* pv = (float*)&v;
    #pragma unroll
    for (int q = 0; q < 4; q++) {
        int src = (q * CC + f) * CC + o;
        pv[q] = Theta1[src] + s8 * Theta1[4*CC*CC + src] + is8 * Theta1[8*CC*CC + src];
    }
    g_Te3[idx] = v;
}

// ---------------- stage 1: stower0 (masking) + tcn0 ----------------
__global__ void __launch_bounds__(256) stage1_kernel(const float* __restrict__ X,
                              const float* __restrict__ Theta0,
                              const float* __restrict__ bias0,
                              const float* __restrict__ Wt0,
                              const float* __restrict__ bt0) {
    __shared__ float4 sR[8][UU][8];   // per-warp per-node tcn staging (32 floats)
    int tid = threadIdx.x;
    int lane = tid & 31;
    int w    = tid >> 5;

    float t0a = __ldg(&Theta0[lane]),      t0b = __ldg(&Theta0[CC + lane]);
    float t0c = __ldg(&Theta0[2*CC+lane]), t0d = __ldg(&Theta0[3*CC + lane]);
    float b0 = __ldg(&bias0[lane]), btc = __ldg(&bt0[lane]);
    float4 wv[8];
    #pragma unroll
    for (int q = 0; q < 8; q++) wv[q] = __ldg(&((const float4*)Wt0)[lane * 8 + q]);

    int warpId = blockIdx.x * 8 + w;
    int nW = gridDim.x * 8;

    for (int grp = warpId; grp < NG; grp += nW) {
        int g0 = grp * UU;
        float o_u[UU];
        #pragma unroll
        for (int u = 0; u < UU; u++) {
            int g = g0 + u;
            int n = g % NN, bt = g / NN;
            int M = g_M[1][n];
            float inv = g_inv[1][n];
            float wt = 0.f, xv = 0.f;
            if (lane < M) {
                float2 wi = g_nwi[1][n][lane];
                wt = wi.x;
                xv = X[bt * NN + __float_as_int(wi.y)];
            }
            float t = wt * xv;
            float sw = t, sw2 = t * xv;
            bool vld = (lane < KK) && (wt > 0.f);
            float mx = vld ? xv : -INFINITY;
            float mn = vld ? xv : INFINITY;
            #pragma unroll
            for (int off = 16; off > 0; off >>= 1) {
                sw  += __shfl_xor_sync(0xffffffffu, sw,  off);
                sw2 += __shfl_xor_sync(0xffffffffu, sw2, off);
                mx = fmaxf(mx, __shfl_xor_sync(0xffffffffu, mx, off));
                mn = fminf(mn, __shfl_xor_sync(0xffffffffu, mn, off));
            }
            float mean = sw * inv;
            float sd   = sqrtf(fmaxf(sw2 * inv - mean * mean, 0.f) + 1e-5f);
            mean = maskf(mean); mx = maskf(mx); mn = maskf(mn); sd = maskf(sd);
            float o = b0 + mean * t0a + mx * t0b + mn * t0c + sd * t0d;
            o_u[u] = o;
            ((float*)&sR[w][u][0])[lane] = o;
        }
        __syncwarp();
        float acc[UU];
        #pragma unroll
        for (int u = 0; u < UU; u++) acc[u] = btc + o_u[u];
        #pragma unroll
        for (int q = 0; q < 8; q++) {
            #pragma unroll
            for (int u = 0; u < UU; u++) {
                float4 r = sR[w][u][q];
                acc[u] += wv[q].x * r.x + wv[q].y * r.y + wv[q].z * r.z + wv[q].w * r.w;
            }
        }
        __syncwarp();
        #pragma unroll
        for (int u = 0; u < UU; u++)
            g_h1[(size_t)(g0 + u) * CC + lane] = ftanh(acc[u]);
    }
}

// ---------------- stage 2: stower1 (folded scalers) + tcn1 + head ----------
__global__ void __launch_bounds__(256) stage2_kernel(const float* __restrict__ Theta1,
                              const float* __restrict__ bias1,
                              const float* __restrict__ Wt1,
                              const float* __restrict__ bt1,
                              const float* __restrict__ Wout,
                              const float* __restrict__ bout,
                              float* __restrict__ out) {
    __shared__ float4 sTe[CC * CC];    // folded Theta1, [f*32+o] = {q0..q3}  (16KB)
    __shared__ float4 sWtv[8 * CC];    // tcn weights [q*32+o] = Wt1[o][4q..]  (4KB)
    __shared__ float4 sS[8][UU][CC];   // per-warp per-node stats / staging   (16KB)
    int tid = threadIdx.x;
    int lane = tid & 31;
    int w    = tid >> 5;

    for (int i = tid; i < CC * CC; i += 256) sTe[i] = g_Te3[i];
    for (int i = tid; i < 8 * CC; i += 256) {
        int q = i >> 5, o = i & 31;
        sWtv[i] = __ldg(&((const float4*)Wt1)[o * 8 + q]);
    }
    float b1 = __ldg(&bias1[lane]), btc = __ldg(&bt1[lane]);
    float wo = __ldg(&Wout[lane]),  bo  = __ldg(&bout[0]);
    __syncthreads();

    int warpId = blockIdx.x * 8 + w;
    int nW = gridDim.x * 8;

    for (int grp = warpId; grp < NG; grp += nW) {
        int g0 = grp * UU;
        int cntOK = 1;
        // ---- phase A: gather + stats ----
        #pragma unroll
        for (int u = 0; u < UU; u++) {
            int g = g0 + u;
            int n = g % NN, bt = g / NN;
            size_t baseC = (size_t)bt * NN * CC + lane;
            int M = g_M[0][n];
            cntOK &= (g_cnt[0][n] == KK);
            float inv = g_inv[0][n];
            const float2* nw = g_nwi[0][n];
            float sw = 0.f, sw2 = 0.f, mx = -INFINITY, mn = INFINITY;
            if (M == KK) {
                #pragma unroll
                for (int j = 0; j < KK; j++) {
                    float2 wi = __ldg(&nw[j]);
                    float hv = __ldg(&g_h1[baseC + (size_t)__float_as_int(wi.y) * CC]);
                    float t = wi.x * hv;
                    sw += t; sw2 += t * hv;
                    if (wi.x > 0.f) { mx = fmaxf(mx, hv); mn = fminf(mn, hv); }
                }
            } else {
                for (int j = 0; j < M; j++) {
                    float2 wi = __ldg(&nw[j]);
                    float hv = __ldg(&g_h1[baseC + (size_t)__float_as_int(wi.y) * CC]);
                    float t = wi.x * hv;
                    sw += t; sw2 += t * hv;
                    if (j < KK && wi.x > 0.f) { mx = fmaxf(mx, hv); mn = fminf(mn, hv); }
                }
            }
            float mean = sw * inv;
            float sd   = sqrtf(fmaxf(sw2 * inv - mean * mean, 0.f) + 1e-5f);
            sS[w][u][lane] = make_float4(mean, mx, mn, sd);
        }
        __syncwarp();

        // ---- phase B: Theta1 matmul ----
        float acc[UU];
        #pragma unroll
        for (int u = 0; u < UU; u++) acc[u] = b1;
        if (cntOK) {
            #pragma unroll 4
            for (int f = 0; f < CC; f++) {
                float4 wv2 = sTe[f * CC + lane];
                #pragma unroll
                for (int u = 0; u < UU; u++) {
                    float4 st = sS[w][u][f];
                    acc[u] += st.x * wv2.x + st.y * wv2.y + st.z * wv2.z + st.w * wv2.w;
                }
            }
        } else {   // rare ties: generic A + s*B + C/s from global Theta1
            #pragma unroll
            for (int u = 0; u < UU; u++) {
                int n = (g0 + u) % NN;
                float s  = log1pf((float)g_cnt[0][n]);
                float is = 1.0f / s;
                float A = 0.f, Bs = 0.f, Cs = 0.f;
                for (int f = 0; f < CC; f++) {
                    float4 st = sS[w][u][f];
                    float mv[4] = {st.x, st.y, st.z, st.w};
                    #pragma unroll
                    for (int q = 0; q < 4; q++) {
                        int i = q * CC + f;
                        A  += mv[q] * Theta1[i * CC + lane];
                        Bs += mv[q] * Theta1[4*CC*CC + i * CC + lane];
                        Cs += mv[q] * Theta1[8*CC*CC + i * CC + lane];
                    }
                }
                acc[u] += A + s * Bs + is * Cs;
            }
        }
        __syncwarp();

        // ---- phase C: relu -> tcn1 -> relu(tanh) -> head ----
        float r_u[UU];
        #pragma unroll
        for (int u = 0; u < UU; u++) {
            r_u[u] = fmaxf(acc[u], 0.f);
            ((float*)&sS[w][u][0])[lane] = r_u[u];
        }
        __syncwarp();
        float acc2[UU];
        #pragma unroll
        for (int u = 0; u < UU; u++) acc2[u] = btc + r_u[u];
        #pragma unroll
        for (int q = 0; q < 8; q++) {
            float4 wq = sWtv[q * CC + lane];
            #pragma unroll
            for (int u = 0; u < UU; u++) {
                float4 rr = ((const float4*)&sS[w][u][0])[q];
                acc2[u] += wq.x * rr.x + wq.y * rr.y + wq.z * rr.z + wq.w * rr.w;
            }
        }
        __syncwarp();
        #pragma unroll
        for (int u = 0; u < UU; u++) {
            float uu = fmaxf(ftanh(acc2[u]), 0.f);
            float p = wo * uu;
            #pragma unroll
            for (int off = 16; off > 0; off >>= 1)
                p += __shfl_xor_sync(0xffffffffu, p, off);
            if (lane == 0) out[g0 + u] = p + bo;
        }
    }
}

extern "C" void kernel_launch(void* const* d_in, const int* in_sizes, int n_in,
                              void* d_out, int out_size) {
    const float* X      = (const float*)d_in[0];
    const float* adj    = (const float*)d_in[1];
    const float* adjm   = (const float*)d_in[2];
    const float* Theta0 = (const float*)d_in[3];
    const float* bias0  = (const float*)d_in[4];
    const float* Wt0    = (const float*)d_in[5];
    const float* bt0    = (const float*)d_in[6];
    const float* Theta1 = (const float*)d_in[7];
    const float* bias1  = (const float*)d_in[8];
    const float* Wt1    = (const float*)d_in[9];
    const float* bt1    = (const float*)d_in[10];
    const float* Wout   = (const float*)d_in[11];
    const float* bout   = (const float*)d_in[12];
    float* out = (float*)d_out;

    prep_kernel<<<4, 256>>>(Theta1);
    topk_kernel<<<(2 * NN * 32 + 255) / 256, 256>>>(adj, adjm);
    stage1_kernel<<<592, 256>>>(X, Theta0, bias0, Wt0, bt0);
    stage2_kernel<<<592, 256>>>(Theta1, bias1, Wt1, bt1, Wout, bout, out);
}

// round 5
// speedup vs baseline: 2.2129x; 1.1757x over previous
#include <cuda_runtime.h>
#include <math.h>

#define Bb 4
#define Tt 12
#define NN 2000
#define KK 8
#define KMAX 16
#define CC 32
#define TOT (Bb*Tt*NN)
#define UU1 4
#define NG1 (TOT/UU1)        // 24000 (stage1)
#define UU2 8
#define NG2 (TOT/UU2)        // 12000 (stage2)

// ---- scratch (no allocations allowed) ----
__device__ float2 g_nwi[2][NN][KMAX];  // (weight, idx-as-bits)
__device__ int    g_M[2][NN];          // stored entries (<=15)
__device__ int    g_cnt[2][NN];        // true kept count
__device__ float  g_inv[2][NN];        // 1/deg
__device__ float  g_h1[(size_t)TOT * CC];
__device__ float4 g_Te3[CC * CC];      // folded Theta1: [f*32+o] = {q=0..3}
__device__ float4 g_Wt1v[8 * CC];      // Wt1 vectorized: [q*32+o] = Wt1[o][4q..4q+3]

typedef unsigned long long ull;

__device__ __forceinline__ float maskf(float v) {
    if (isnan(v)) v = 6.0f;
    if (isinf(v)) v = 0.0f;
    return fminf(v, 6.0f);
}
__device__ __forceinline__ float ftanh(float x) {
    float e = __expf(2.0f * x);
    return 1.0f - __fdividef(2.0f, e + 1.0f);
}
__device__ __forceinline__ ull pk2(float a, float b) {
    ull r; asm("mov.b64 %0, {%1,%2};" : "=l"(r) : "f"(a), "f"(b)); return r;
}
__device__ __forceinline__ void upk2(ull v, float& a, float& b) {
    asm("mov.b64 {%0,%1}, %2;" : "=f"(a), "=f"(b) : "l"(v));
}
__device__ __forceinline__ ull fma2(ull a, ull b, ull c) {
    ull d; asm("fma.rn.f32x2 %0, %1, %2, %3;" : "=l"(d) : "l"(a), "l"(b), "l"(c)); return d;
}
__device__ __forceinline__ ull add2(ull a, ull b) {
    ull d; asm("add.rn.f32x2 %0, %1, %2;" : "=l"(d) : "l"(a), "l"(b)); return d;
}

// ---------------- top-K: warp per row (unchanged, exact tie semantics) ------
__global__ void __launch_bounds__(256) topk_kernel(const float* __restrict__ adj,
                                                   const float* __restrict__ adjm) {
    int gw = (blockIdx.x * 256 + threadIdx.x) >> 5;
    if (gw >= 2 * NN) return;
    int mat = gw / NN;
    int row = gw - mat * NN;
    const float4* src4 = (const float4*)((mat == 0 ? adj : adjm) + (size_t)row * NN);
    int lane = threadIdx.x & 31;
    unsigned lt = (1u << lane) - 1u;

    float v0=-INFINITY,v1=-INFINITY,v2=-INFINITY,v3=-INFINITY,
          v4=-INFINITY,v5=-INFINITY,v6=-INFINITY,v7=-INFINITY;

    #define INS(xx) do { float x_ = (xx); \
        v7 = fmaxf(v7, fminf(v6, x_)); \
        v6 = fmaxf(v6, fminf(v5, x_)); \
        v5 = fmaxf(v5, fminf(v4, x_)); \
        v4 = fmaxf(v4, fminf(v3, x_)); \
        v3 = fmaxf(v3, fminf(v2, x_)); \
        v2 = fmaxf(v2, fminf(v1, x_)); \
        v1 = fmaxf(v1, fminf(v0, x_)); \
        v0 = fmaxf(v0, x_); } while(0)

    #pragma unroll 4
    for (int t = 0; t < 16; t++) {
        int i4 = lane + t * 32;
        if (i4 < 500) {
            float4 f = __ldg(&src4[i4]);
            INS(f.x); INS(f.y); INS(f.z); INS(f.w);
        }
    }
    #undef INS

    float thr = -INFINITY;
    #pragma unroll
    for (int k = 0; k < 8; k++) {
        float cv = v0; int cl = lane;
        #pragma unroll
        for (int off = 16; off > 0; off >>= 1) {
            float ov = __shfl_xor_sync(0xffffffffu, cv, off);
            int   ol = __shfl_xor_sync(0xffffffffu, cl, off);
            if (ov > cv || (ov == cv && ol < cl)) { cv = ov; cl = ol; }
        }
        if (cl == lane) { v0=v1; v1=v2; v2=v3; v3=v4; v4=v5; v5=v6; v6=v7; v7=-INFINITY; }
        thr = cv;
    }

    int cgt = 0, ceq = 0;
    float sgt = 0.f;
    for (int t = 0; t < 16; t++) {
        int i4 = lane + t * 32;
        float4 f;
        if (i4 < 500) f = __ldg(&src4[i4]);
        else { f.x=f.y=f.z=f.w=-INFINITY; }
        bool any = (f.x >= thr) | (f.y >= thr) | (f.z >= thr) | (f.w >= thr);
        if (__ballot_sync(0xffffffffu, any) == 0u) continue;
        int ib = 4 * i4;
        #pragma unroll
        for (int s = 0; s < 4; s++) {
            float x = (s==0)?f.x:(s==1)?f.y:(s==2)?f.z:f.w;
            int   i = ib + s;
            bool gt = x >  thr;
            bool ge = x >= thr;
            unsigned mgt = __ballot_sync(0xffffffffu, gt);
            unsigned mge = __ballot_sync(0xffffffffu, ge);
            unsigned meq = mge & ~mgt;
            if (gt) {
                int p = cgt + __popc(mgt & lt);
                g_nwi[mat][row][p] = make_float2(x, __int_as_float(i));
                sgt += x;
            }
            cgt += __popc(mgt);
            if (meq) {
                if (ge && !gt) {
                    int p = ceq + __popc(meq & lt);
                    if (p < 8) g_nwi[mat][row][8 + p] = make_float2(x, __int_as_float(i));
                }
                ceq += __popc(meq);
            }
        }
    }
    #pragma unroll
    for (int off = 16; off > 0; off >>= 1)
        sgt += __shfl_xor_sync(0xffffffffu, sgt, off);

    if (lane == 0) {
        int cnt = cgt + ceq;
        int eq_stored = ceq < 8 ? ceq : 8;
        int M = cgt + eq_stored;
        for (int e = 0; e < eq_stored; e++)
            g_nwi[mat][row][cgt + e] = g_nwi[mat][row][8 + e];
        g_M[mat][row]   = M;
        g_cnt[mat][row] = cnt;
        g_inv[mat][row] = 1.0f / (sgt + (float)ceq * thr);
    }
}

// ---------------- prep: fold Theta1, vectorize Wt1 ----------------
__global__ void __launch_bounds__(256) prep_kernel(const float* __restrict__ Theta1,
                                                   const float* __restrict__ Wt1) {
    int idx = blockIdx.x * 256 + threadIdx.x;
    if (idx < CC * CC) {
        int f = idx >> 5, o = idx & 31;
        const float s8  = log1pf(8.0f);
        const float is8 = 1.0f / s8;
        float4 v;
        float* pv = (float*)&v;
        #pragma unroll
        for (int q = 0; q < 4; q++) {
            int src = (q * CC + f) * CC + o;
            pv[q] = Theta1[src] + s8 * Theta1[4*CC*CC + src] + is8 * Theta1[8*CC*CC + src];
        }
        g_Te3[idx] = v;
    } else if (idx < CC * CC + 8 * CC) {
        int i = idx - CC * CC;
        int q = i >> 5, o = i & 31;
        g_Wt1v[i] = ((const float4*)Wt1)[o * 8 + q];
    }
}

// ---------------- stage 1: stower0 (masking) + tcn0 ----------------
__global__ void __launch_bounds__(256) stage1_kernel(const float* __restrict__ X,
                              const float* __restrict__ Theta0,
                              const float* __restrict__ bias0,
                              const float* __restrict__ Wt0,
                              const float* __restrict__ bt0) {
    __shared__ float4 sR[8][UU1][8];
    int tid = threadIdx.x;
    int lane = tid & 31;
    int w    = tid >> 5;

    float t0a = __ldg(&Theta0[lane]),      t0b = __ldg(&Theta0[CC + lane]);
    float t0c = __ldg(&Theta0[2*CC+lane]), t0d = __ldg(&Theta0[3*CC + lane]);
    float b0 = __ldg(&bias0[lane]), btc = __ldg(&bt0[lane]);
    float4 wv[8];
    #pragma unroll
    for (int q = 0; q < 8; q++) wv[q] = __ldg(&((const float4*)Wt0)[lane * 8 + q]);

    int warpId = blockIdx.x * 8 + w;
    int nW = gridDim.x * 8;

    for (int grp = warpId; grp < NG1; grp += nW) {
        int g0 = grp * UU1;
        float o_u[UU1];
        #pragma unroll
        for (int u = 0; u < UU1; u++) {
            int g = g0 + u;
            int n = g % NN, bt = g / NN;
            int M = g_M[1][n];
            float inv = g_inv[1][n];
            float wt = 0.f, xv = 0.f;
            if (lane < M) {
                float2 wi = g_nwi[1][n][lane];
                wt = wi.x;
                xv = X[bt * NN + __float_as_int(wi.y)];
            }
            float t = wt * xv;
            float sw = t, sw2 = t * xv;
            bool vld = (lane < KK) && (wt > 0.f);
            float mx = vld ? xv : -INFINITY;
            float mn = vld ? xv : INFINITY;
            #pragma unroll
            for (int off = 16; off > 0; off >>= 1) {
                sw  += __shfl_xor_sync(0xffffffffu, sw,  off);
                sw2 += __shfl_xor_sync(0xffffffffu, sw2, off);
                mx = fmaxf(mx, __shfl_xor_sync(0xffffffffu, mx, off));
                mn = fminf(mn, __shfl_xor_sync(0xffffffffu, mn, off));
            }
            float mean = sw * inv;
            float sd   = sqrtf(fmaxf(sw2 * inv - mean * mean, 0.f) + 1e-5f);
            mean = maskf(mean); mx = maskf(mx); mn = maskf(mn); sd = maskf(sd);
            float o = b0 + mean * t0a + mx * t0b + mn * t0c + sd * t0d;
            o_u[u] = o;
            ((float*)&sR[w][u][0])[lane] = o;
        }
        __syncwarp();
        float acc[UU1];
        #pragma unroll
        for (int u = 0; u < UU1; u++) acc[u] = btc + o_u[u];
        #pragma unroll
        for (int q = 0; q < 8; q++) {
            #pragma unroll
            for (int u = 0; u < UU1; u++) {
                float4 r = sR[w][u][q];
                acc[u] += wv[q].x * r.x + wv[q].y * r.y + wv[q].z * r.z + wv[q].w * r.w;
            }
        }
        __syncwarp();
        #pragma unroll
        for (int u = 0; u < UU1; u++)
            g_h1[(size_t)(g0 + u) * CC + lane] = ftanh(acc[u]);
    }
}

// ---------------- stage 2: stower1 (folded) + tcn1 + head, 8 nodes/warp -----
// f32x2-packed: node pairs share a 64-bit register lane.
__global__ void __launch_bounds__(256) stage2_kernel(const float* __restrict__ Theta1,
                              const float* __restrict__ bias1,
                              const float* __restrict__ bt1,
                              const float* __restrict__ Wout,
                              const float* __restrict__ bout,
                              float* __restrict__ out) {
    // stats, pair-packed: [warp][pair][half][f]; half0=(mean0,mean1,mx0,mx1),
    // half1=(mn0,mn1,sd0,sd1). Aliased as float2 r-staging in phase C.
    __shared__ float4 sP[8][4][2][CC];   // 32 KB
    int tid = threadIdx.x;
    int lane = tid & 31;
    int w    = tid >> 5;

    float b1 = __ldg(&bias1[lane]), btc = __ldg(&bt1[lane]);
    float wo = __ldg(&Wout[lane]),  bo  = __ldg(&bout[0]);

    int warpId = blockIdx.x * 8 + w;
    int nW = gridDim.x * 8;

    for (int grp = warpId; grp < NG2; grp += nW) {
        int g0 = grp * UU2;
        int cntOK = 1;

        // ---- phase A: gather + stats, packed by node pair ----
        #pragma unroll
        for (int p = 0; p < 4; p++) {
            float stm[2], stx[2], stn[2], sts[2];
            #pragma unroll
            for (int e = 0; e < 2; e++) {
                int g = g0 + 2 * p + e;
                int n = g % NN, bt = g / NN;
                size_t baseC = (size_t)bt * NN * CC + lane;
                int M = g_M[0][n];
                cntOK &= (g_cnt[0][n] == KK);
                float inv = g_inv[0][n];
                const float2* nw = g_nwi[0][n];
                float sw = 0.f, sw2 = 0.f, mx = -INFINITY, mn = INFINITY;
                if (M == KK) {
                    #pragma unroll
                    for (int j = 0; j < KK; j++) {
                        float2 wi = __ldg(&nw[j]);
                        float hv = __ldg(&g_h1[baseC + (size_t)__float_as_int(wi.y) * CC]);
                        float t = wi.x * hv;
                        sw += t; sw2 += t * hv;
                        if (wi.x > 0.f) { mx = fmaxf(mx, hv); mn = fminf(mn, hv); }
                    }
                } else {
                    for (int j = 0; j < M; j++) {
                        float2 wi = __ldg(&nw[j]);
                        float hv = __ldg(&g_h1[baseC + (size_t)__float_as_int(wi.y) * CC]);
                        float t = wi.x * hv;
                        sw += t; sw2 += t * hv;
                        if (j < KK && wi.x > 0.f) { mx = fmaxf(mx, hv); mn = fminf(mn, hv); }
                    }
                }
                float mean = sw * inv;
                float sd   = sqrtf(fmaxf(sw2 * inv - mean * mean, 0.f) + 1e-5f);
                stm[e] = mean; stx[e] = mx; stn[e] = mn; sts[e] = sd;
            }
            sP[w][p][0][lane] = make_float4(stm[0], stm[1], stx[0], stx[1]);
            sP[w][p][1][lane] = make_float4(stn[0], stn[1], sts[0], sts[1]);
        }
        __syncwarp();

        // ---- phase B: Theta matmul (folded Te, f32x2) ----
        ull acc[4];
        #pragma unroll
        for (int p = 0; p < 4; p++) acc[p] = pk2(b1, b1);

        if (cntOK) {
            #pragma unroll 4
            for (int f = 0; f < CC; f++) {
                float4 wv = __ldg(&g_Te3[f * CC + lane]);
                ull wx = pk2(wv.x, wv.x), wy = pk2(wv.y, wv.y);
                ull wz = pk2(wv.z, wv.z), ww2 = pk2(wv.w, wv.w);
                #pragma unroll
                for (int p = 0; p < 4; p++) {
                    ulonglong2 a = *(const ulonglong2*)&sP[w][p][0][f];
                    ulonglong2 b = *(const ulonglong2*)&sP[w][p][1][f];
                    acc[p] = fma2(a.x, wx, acc[p]);
                    acc[p] = fma2(a.y, wy, acc[p]);
                    acc[p] = fma2(b.x, wz, acc[p]);
                    acc[p] = fma2(b.y, ww2, acc[p]);
                }
            }
        } else {   // rare ties: generic A + s*B + C/s from global Theta1
            #pragma unroll
            for (int p = 0; p < 4; p++) {
                float accs[2];
                #pragma unroll
                for (int e = 0; e < 2; e++) {
                    int n = (g0 + 2 * p + e) % NN;
                    float s  = log1pf((float)g_cnt[0][n]);
                    float is = 1.0f / s;
                    float A = 0.f, Bs = 0.f, Cs = 0.f;
                    for (int f = 0; f < CC; f++) {
                        float4 a = sP[w][p][0][f];
                        float4 b = sP[w][p][1][f];
                        float mv[4];
                        mv[0] = e ? a.y : a.x;  // mean
                        mv[1] = e ? a.w : a.z;  // mx
                        mv[2] = e ? b.y : b.x;  // mn
                        mv[3] = e ? b.w : b.z;  // sd
                        #pragma unroll
                        for (int q = 0; q < 4; q++) {
                            int i = q * CC + f;
                            A  += mv[q] * Theta1[i * CC + lane];
                            Bs += mv[q] * Theta1[4*CC*CC + i * CC + lane];
                            Cs += mv[q] * Theta1[8*CC*CC + i * CC + lane];
                        }
                    }
                    accs[e] = b1 + A + s * Bs + is * Cs;
                }
                acc[p] = pk2(accs[0], accs[1]);
            }
        }
        __syncwarp();   // all lanes done reading sP

        // ---- phase C: relu -> tcn1 (f32x2) ----
        float2* rp = (float2*)&sP[w][0][0][0];  // alias: [pair*32 + c]
        ull racc[4];
        #pragma unroll
        for (int p = 0; p < 4; p++) {
            float a0, a1; upk2(acc[p], a0, a1);
            float r0 = fmaxf(a0, 0.f), r1 = fmaxf(a1, 0.f);
            rp[p * 32 + lane] = make_float2(r0, r1);
            racc[p] = pk2(r0, r1);
        }
        __syncwarp();

        ull acc2[4];
        ull btc2 = pk2(btc, btc);
        #pragma unroll
        for (int p = 0; p < 4; p++) acc2[p] = add2(btc2, racc[p]);
        #pragma unroll
        for (int q = 0; q < 8; q++) {
            float4 wq = __ldg(&g_Wt1v[q * CC + lane]);
            ull wx = pk2(wq.x, wq.x), wy = pk2(wq.y, wq.y);
            ull wz = pk2(wq.z, wq.z), ww2 = pk2(wq.w, wq.w);
            #pragma unroll
            for (int p = 0; p < 4; p++) {
                const ulonglong2* rr = (const ulonglong2*)&rp[p * 32 + 4 * q];
                ulonglong2 ra = rr[0];
                ulonglong2 rb = rr[1];
                acc2[p] = fma2(ra.x, wx, acc2[p]);
                acc2[p] = fma2(ra.y, wy, acc2[p]);
                acc2[p] = fma2(rb.x, wz, acc2[p]);
                acc2[p] = fma2(rb.y, ww2, acc2[p]);
            }
        }
        __syncwarp();   // done reading rp before next iteration reuses sP

        // ---- head: relu(tanh) -> Wout dot + bout ----
        #pragma unroll
        for (int p = 0; p < 4; p++) {
            float t0, t1; upk2(acc2[p], t0, t1);
            float u0 = fmaxf(ftanh(t0), 0.f);
            float u1 = fmaxf(ftanh(t1), 0.f);
            ull pu = pk2(wo * u0, wo * u1);
            #pragma unroll
            for (int off = 16; off > 0; off >>= 1)
                pu = add2(pu, __shfl_xor_sync(0xffffffffu, pu, off));
            if (lane == 0) {
                float s0, s1; upk2(pu, s0, s1);
                *(float2*)&out[g0 + 2 * p] = make_float2(s0 + bo, s1 + bo);
            }
        }
    }
}

extern "C" void kernel_launch(void* const* d_in, const int* in_sizes, int n_in,
                              void* d_out, int out_size) {
    const float* X      = (const float*)d_in[0];
    const float* adj    = (const float*)d_in[1];
    const float* adjm   = (const float*)d_in[2];
    const float* Theta0 = (const float*)d_in[3];
    const float* bias0  = (const float*)d_in[4];
    const float* Wt0    = (const float*)d_in[5];
    const float* bt0    = (const float*)d_in[6];
    const float* Theta1 = (const float*)d_in[7];
    const float* bias1  = (const float*)d_in[8];
    const float* Wt1    = (const float*)d_in[9];
    const float* bt1    = (const float*)d_in[10];
    const float* Wout   = (const float*)d_in[11];
    const float* bout   = (const float*)d_in[12];
    float* out = (float*)d_out;

    prep_kernel<<<5, 256>>>(Theta1, Wt1);
    topk_kernel<<<(2 * NN * 32 + 255) / 256, 256>>>(adj, adjm);
    stage1_kernel<<<750, 256>>>(X, Theta0, bias0, Wt0, bt0);
    stage2_kernel<<<750, 256>>>(Theta1, bias1, bt1, Wout, bout, out);
}

// round 6
// speedup vs baseline: 2.3028x; 1.0406x over previous
#include <cuda_runtime.h>
#include <math.h>

#define Bb 4
#define Tt 12
#define NN 2000
#define KK 8
#define KMAX 16
#define CC 32
#define TOT (Bb*Tt*NN)
#define UU1 4
#define NG1 (TOT/UU1)        // 24000 (stage1)
#define TB  16               // bt per stage2 group
#define NTB (Bb*Tt/TB)       // 3 bt-blocks
#define NG2 (NN*NTB)         // 6000 stage2 groups

// ---- scratch (no allocations allowed) ----
__device__ float2 g_nwi[2][NN][KMAX];  // (weight, idx-as-bits)
__device__ int    g_M[2][NN];          // stored entries (<=15)
__device__ int    g_cnt[2][NN];        // true kept count
__device__ float  g_inv[2][NN];        // 1/deg
__device__ float  g_h1[(size_t)TOT * CC];
__device__ float4 g_Te3[CC * CC];      // folded Theta1 (s=log1p(8)): [f*32+o] = {q0..q3}
__device__ float4 g_TeA[CC * CC];      // Theta1 block A vectorized
__device__ float4 g_TeB[CC * CC];      // block B (scaled by s)
__device__ float4 g_TeC[CC * CC];      // block C (scaled by 1/s)
__device__ float4 g_Wt1v[8 * CC];      // Wt1 vectorized: [q*32+o] = Wt1[o][4q..4q+3]

typedef unsigned long long ull;

__device__ __forceinline__ float maskf(float v) {
    if (isnan(v)) v = 6.0f;
    if (isinf(v)) v = 0.0f;
    return fminf(v, 6.0f);
}
__device__ __forceinline__ float ftanh(float x) {
    float e = __expf(2.0f * x);
    return 1.0f - __fdividef(2.0f, e + 1.0f);
}
__device__ __forceinline__ ull pk2(float a, float b) {
    ull r; asm("mov.b64 %0, {%1,%2};" : "=l"(r) : "f"(a), "f"(b)); return r;
}
__device__ __forceinline__ void upk2(ull v, float& a, float& b) {
    asm("mov.b64 {%0,%1}, %2;" : "=f"(a), "=f"(b) : "l"(v));
}
__device__ __forceinline__ ull fma2(ull a, ull b, ull c) {
    ull d; asm("fma.rn.f32x2 %0, %1, %2, %3;" : "=l"(d) : "l"(a), "l"(b), "l"(c)); return d;
}
__device__ __forceinline__ ull add2(ull a, ull b) {
    ull d; asm("add.rn.f32x2 %0, %1, %2;" : "=l"(d) : "l"(a), "l"(b)); return d;
}

// ---------------- top-K: warp per row (exact tie semantics) ----------------
__global__ void __launch_bounds__(256) topk_kernel(const float* __restrict__ adj,
                                                   const float* __restrict__ adjm) {
    int gw = (blockIdx.x * 256 + threadIdx.x) >> 5;
    if (gw >= 2 * NN) return;
    int mat = gw / NN;
    int row = gw - mat * NN;
    const float4* src4 = (const float4*)((mat == 0 ? adj : adjm) + (size_t)row * NN);
    int lane = threadIdx.x & 31;
    unsigned lt = (1u << lane) - 1u;

    float v0=-INFINITY,v1=-INFINITY,v2=-INFINITY,v3=-INFINITY,
          v4=-INFINITY,v5=-INFINITY,v6=-INFINITY,v7=-INFINITY;

    #define INS(xx) do { float x_ = (xx); \
        v7 = fmaxf(v7, fminf(v6, x_)); \
        v6 = fmaxf(v6, fminf(v5, x_)); \
        v5 = fmaxf(v5, fminf(v4, x_)); \
        v4 = fmaxf(v4, fminf(v3, x_)); \
        v3 = fmaxf(v3, fminf(v2, x_)); \
        v2 = fmaxf(v2, fminf(v1, x_)); \
        v1 = fmaxf(v1, fminf(v0, x_)); \
        v0 = fmaxf(v0, x_); } while(0)

    #pragma unroll 4
    for (int t = 0; t < 16; t++) {
        int i4 = lane + t * 32;
        if (i4 < 500) {
            float4 f = __ldg(&src4[i4]);
            INS(f.x); INS(f.y); INS(f.z); INS(f.w);
        }
    }
    #undef INS

    float thr = -INFINITY;
    #pragma unroll
    for (int k = 0; k < 8; k++) {
        float cv = v0; int cl = lane;
        #pragma unroll
        for (int off = 16; off > 0; off >>= 1) {
            float ov = __shfl_xor_sync(0xffffffffu, cv, off);
            int   ol = __shfl_xor_sync(0xffffffffu, cl, off);
            if (ov > cv || (ov == cv && ol < cl)) { cv = ov; cl = ol; }
        }
        if (cl == lane) { v0=v1; v1=v2; v2=v3; v3=v4; v4=v5; v5=v6; v6=v7; v7=-INFINITY; }
        thr = cv;
    }

    int cgt = 0, ceq = 0;
    float sgt = 0.f;
    for (int t = 0; t < 16; t++) {
        int i4 = lane + t * 32;
        float4 f;
        if (i4 < 500) f = __ldg(&src4[i4]);
        else { f.x=f.y=f.z=f.w=-INFINITY; }
        bool any = (f.x >= thr) | (f.y >= thr) | (f.z >= thr) | (f.w >= thr);
        if (__ballot_sync(0xffffffffu, any) == 0u) continue;
        int ib = 4 * i4;
        #pragma unroll
        for (int s = 0; s < 4; s++) {
            float x = (s==0)?f.x:(s==1)?f.y:(s==2)?f.z:f.w;
            int   i = ib + s;
            bool gt = x >  thr;
            bool ge = x >= thr;
            unsigned mgt = __ballot_sync(0xffffffffu, gt);
            unsigned mge = __ballot_sync(0xffffffffu, ge);
            unsigned meq = mge & ~mgt;
            if (gt) {
                int p = cgt + __popc(mgt & lt);
                g_nwi[mat][row][p] = make_float2(x, __int_as_float(i));
                sgt += x;
            }
            cgt += __popc(mgt);
            if (meq) {
                if (ge && !gt) {
                    int p = ceq + __popc(meq & lt);
                    if (p < 8) g_nwi[mat][row][8 + p] = make_float2(x, __int_as_float(i));
                }
                ceq += __popc(meq);
            }
        }
    }
    #pragma unroll
    for (int off = 16; off > 0; off >>= 1)
        sgt += __shfl_xor_sync(0xffffffffu, sgt, off);

    if (lane == 0) {
        int cnt = cgt + ceq;
        int eq_stored = ceq < 8 ? ceq : 8;
        int M = cgt + eq_stored;
        for (int e = 0; e < eq_stored; e++)
            g_nwi[mat][row][cgt + e] = g_nwi[mat][row][8 + e];
        g_M[mat][row]   = M;
        g_cnt[mat][row] = cnt;
        g_inv[mat][row] = 1.0f / (sgt + (float)ceq * thr);
    }
}

// ---------------- prep: fold + vectorize weights ----------------
__global__ void __launch_bounds__(256) prep_kernel(const float* __restrict__ Theta1,
                                                   const float* __restrict__ Wt1) {
    int idx = blockIdx.x * 256 + threadIdx.x;
    if (idx < CC * CC) {
        int f = idx >> 5, o = idx & 31;
        const float s8  = log1pf(8.0f);
        const float is8 = 1.0f / s8;
        float4 va, vb, vc, ve;
        float *pa=(float*)&va, *pb=(float*)&vb, *pc=(float*)&vc, *pe=(float*)&ve;
        #pragma unroll
        for (int q = 0; q < 4; q++) {
            int src = (q * CC + f) * CC + o;
            float A = Theta1[src];
            float B = Theta1[4*CC*CC + src];
            float C = Theta1[8*CC*CC + src];
            pa[q] = A; pb[q] = B; pc[q] = C;
            pe[q] = A + s8 * B + is8 * C;
        }
        g_TeA[idx] = va; g_TeB[idx] = vb; g_TeC[idx] = vc; g_Te3[idx] = ve;
    } else if (idx < CC * CC + 8 * CC) {
        int i = idx - CC * CC;
        int q = i >> 5, o = i & 31;
        g_Wt1v[i] = ((const float4*)Wt1)[o * 8 + q];
    }
}

// ---------------- stage 1: stower0 (masking) + tcn0 ----------------
__global__ void __launch_bounds__(256) stage1_kernel(const float* __restrict__ X,
                              const float* __restrict__ Theta0,
                              const float* __restrict__ bias0,
                              const float* __restrict__ Wt0,
                              const float* __restrict__ bt0) {
    __shared__ float4 sR[8][UU1][8];
    int tid = threadIdx.x;
    int lane = tid & 31;
    int w    = tid >> 5;

    float t0a = __ldg(&Theta0[lane]),      t0b = __ldg(&Theta0[CC + lane]);
    float t0c = __ldg(&Theta0[2*CC+lane]), t0d = __ldg(&Theta0[3*CC + lane]);
    float b0 = __ldg(&bias0[lane]), btc = __ldg(&bt0[lane]);
    float4 wv[8];
    #pragma unroll
    for (int q = 0; q < 8; q++) wv[q] = __ldg(&((const float4*)Wt0)[lane * 8 + q]);

    int warpId = blockIdx.x * 8 + w;
    int nW = gridDim.x * 8;

    for (int grp = warpId; grp < NG1; grp += nW) {
        int g0 = grp * UU1;
        float o_u[UU1];
        #pragma unroll
        for (int u = 0; u < UU1; u++) {
            int g = g0 + u;
            int n = g % NN, bt = g / NN;
            int M = g_M[1][n];
            float inv = g_inv[1][n];
            float wt = 0.f, xv = 0.f;
            if (lane < M) {
                float2 wi = g_nwi[1][n][lane];
                wt = wi.x;
                xv = X[bt * NN + __float_as_int(wi.y)];
            }
            float t = wt * xv;
            float sw = t, sw2 = t * xv;
            bool vld = (lane < KK) && (wt > 0.f);
            float mx = vld ? xv : -INFINITY;
            float mn = vld ? xv : INFINITY;
            #pragma unroll
            for (int off = 16; off > 0; off >>= 1) {
                sw  += __shfl_xor_sync(0xffffffffu, sw,  off);
                sw2 += __shfl_xor_sync(0xffffffffu, sw2, off);
                mx = fmaxf(mx, __shfl_xor_sync(0xffffffffu, mx, off));
                mn = fminf(mn, __shfl_xor_sync(0xffffffffu, mn, off));
            }
            float mean = sw * inv;
            float sd   = sqrtf(fmaxf(sw2 * inv - mean * mean, 0.f) + 1e-5f);
            mean = maskf(mean); mx = maskf(mx); mn = maskf(mn); sd = maskf(sd);
            float o = b0 + mean * t0a + mx * t0b + mn * t0c + sd * t0d;
            o_u[u] = o;
            ((float*)&sR[w][u][0])[lane] = o;
        }
        __syncwarp();
        float acc[UU1];
        #pragma unroll
        for (int u = 0; u < UU1; u++) acc[u] = btc + o_u[u];
        #pragma unroll
        for (int q = 0; q < 8; q++) {
            #pragma unroll
            for (int u = 0; u < UU1; u++) {
                float4 r = sR[w][u][q];
                acc[u] += wv[q].x * r.x + wv[q].y * r.y + wv[q].z * r.z + wv[q].w * r.w;
            }
        }
        __syncwarp();
        #pragma unroll
        for (int u = 0; u < UU1; u++)
            g_h1[(size_t)(g0 + u) * CC + lane] = ftanh(acc[u]);
    }
}

// ---------------- stage 2: n-major, 16 bt per warp, f32x2 ----------------
__global__ void __launch_bounds__(128) stage2_kernel(const float* __restrict__ bias1,
                              const float* __restrict__ bt1,
                              const float* __restrict__ Wout,
                              const float* __restrict__ bout,
                              float* __restrict__ out) {
    __shared__ float4 sP[4][8][2][CC];   // 32 KB: [warp][pair][half][f]
    int tid = threadIdx.x;
    int lane = tid & 31;
    int w    = tid >> 5;

    float b1 = __ldg(&bias1[lane]), btc = __ldg(&bt1[lane]);
    float wo = __ldg(&Wout[lane]),  bo  = __ldg(&bout[0]);

    int warpId = blockIdx.x * 4 + w;
    int nW = gridDim.x * 4;

    for (int grp = warpId; grp < NG2; grp += nW) {
        int n  = grp / NTB;
        int tb = grp - n * NTB;
        int bt0v = tb * TB;

        int M   = g_M[0][n];
        int cnt = g_cnt[0][n];
        float inv = g_inv[0][n];
        bool fast = (cnt == KK);

        // neighbor list once per group: lane j holds entry j
        float wreg = 0.f; int ireg = 0;
        if (lane < M) {
            float2 wi = g_nwi[0][n][lane];
            wreg = wi.x; ireg = __float_as_int(wi.y);
        }

        // ---- phase A: gather + stats for 16 bt, j-outer for MLP ----
        float sw[TB], sw2[TB], mxv[TB], mnv[TB];
        #pragma unroll
        for (int u = 0; u < TB; u++) {
            sw[u] = 0.f; sw2[u] = 0.f; mxv[u] = -INFINITY; mnv[u] = INFINITY;
        }
        size_t cbase = (size_t)bt0v * NN * CC + lane;
        for (int j = 0; j < M; j++) {
            float wtj = __shfl_sync(0xffffffffu, wreg, j);
            int   mij = __shfl_sync(0xffffffffu, ireg, j);
            const float* hp = g_h1 + cbase + (size_t)mij * CC;
            bool pos = (j < KK) && (wtj > 0.f);
            if (pos) {
                #pragma unroll
                for (int u = 0; u < TB; u++) {
                    float hv = __ldg(hp + (size_t)u * (NN * CC));
                    float t = wtj * hv;
                    sw[u] += t; sw2[u] += t * hv;
                    mxv[u] = fmaxf(mxv[u], hv); mnv[u] = fminf(mnv[u], hv);
                }
            } else {
                #pragma unroll
                for (int u = 0; u < TB; u++) {
                    float hv = __ldg(hp + (size_t)u * (NN * CC));
                    float t = wtj * hv;
                    sw[u] += t; sw2[u] += t * hv;
                }
            }
        }
        #pragma unroll
        for (int u = 0; u < TB; u++) {
            float mean = sw[u] * inv;
            float sd = sqrtf(fmaxf(sw2[u] * inv - mean * mean, 0.f) + 1e-5f);
            sw[u] = mean; sw2[u] = sd;   // reuse regs
        }
        #pragma unroll
        for (int p = 0; p < 8; p++) {
            int u0 = 2 * p, u1 = 2 * p + 1;
            sP[w][p][0][lane] = make_float4(sw[u0], sw[u1], mxv[u0], mxv[u1]);
            sP[w][p][1][lane] = make_float4(mnv[u0], mnv[u1], sw2[u0], sw2[u1]);
        }
        __syncwarp();

        // ---- phase B: Theta matmul ----
        ull acc[8];
        #pragma unroll
        for (int p = 0; p < 8; p++) acc[p] = pk2(b1, b1);

        if (fast) {
            #pragma unroll 2
            for (int f = 0; f < CC; f++) {
                float4 wv = __ldg(&g_Te3[f * CC + lane]);
                ull wx = pk2(wv.x, wv.x), wy = pk2(wv.y, wv.y);
                ull wz = pk2(wv.z, wv.z), ww2 = pk2(wv.w, wv.w);
                #pragma unroll
                for (int p = 0; p < 8; p++) {
                    ulonglong2 a = *(const ulonglong2*)&sP[w][p][0][f];
                    ulonglong2 b = *(const ulonglong2*)&sP[w][p][1][f];
                    acc[p] = fma2(a.x, wx, acc[p]);
                    acc[p] = fma2(a.y, wy, acc[p]);
                    acc[p] = fma2(b.x, wz, acc[p]);
                    acc[p] = fma2(b.y, ww2, acc[p]);
                }
            }
        } else {   // ties: s = log1p(cnt) uniform per n; fold on the fly
            float s  = log1pf((float)cnt);
            float is = 1.0f / s;
            for (int f = 0; f < CC; f++) {
                float4 a4 = __ldg(&g_TeA[f * CC + lane]);
                float4 b4 = __ldg(&g_TeB[f * CC + lane]);
                float4 c4 = __ldg(&g_TeC[f * CC + lane]);
                float4 wv;
                wv.x = a4.x + s * b4.x + is * c4.x;
                wv.y = a4.y + s * b4.y + is * c4.y;
                wv.z = a4.z + s * b4.z + is * c4.z;
                wv.w = a4.w + s * b4.w + is * c4.w;
                ull wx = pk2(wv.x, wv.x), wy = pk2(wv.y, wv.y);
                ull wz = pk2(wv.z, wv.z), ww2 = pk2(wv.w, wv.w);
                #pragma unroll
                for (int p = 0; p < 8; p++) {
                    ulonglong2 a = *(const ulonglong2*)&sP[w][p][0][f];
                    ulonglong2 b = *(const ulonglong2*)&sP[w][p][1][f];
                    acc[p] = fma2(a.x, wx, acc[p]);
                    acc[p] = fma2(a.y, wy, acc[p]);
                    acc[p] = fma2(b.x, wz, acc[p]);
                    acc[p] = fma2(b.y, ww2, acc[p]);
                }
            }
        }
        __syncwarp();   // done reading sP stats

        // ---- phase C: relu -> tcn1 (f32x2) ----
        float2* rp = (float2*)&sP[w][0][0][0];   // 8 pairs x 32 float2
        ull racc[8];
        #pragma unroll
        for (int p = 0; p < 8; p++) {
            float a0, a1; upk2(acc[p], a0, a1);
            float r0 = fmaxf(a0, 0.f), r1 = fmaxf(a1, 0.f);
            rp[p * 32 + lane] = make_float2(r0, r1);
            racc[p] = pk2(r0, r1);
        }
        __syncwarp();

        ull acc2[8];
        ull btc2 = pk2(btc, btc);
        #pragma unroll
        for (int p = 0; p < 8; p++) acc2[p] = add2(btc2, racc[p]);
        #pragma unroll
        for (int q = 0; q < 8; q++) {
            float4 wq = __ldg(&g_Wt1v[q * CC + lane]);
            ull wx = pk2(wq.x, wq.x), wy = pk2(wq.y, wq.y);
            ull wz = pk2(wq.z, wq.z), ww2 = pk2(wq.w, wq.w);
            #pragma unroll
            for (int p = 0; p < 8; p++) {
                const ulonglong2* rr = (const ulonglong2*)&rp[p * 32 + 4 * q];
                ulonglong2 ra = rr[0];
                ulonglong2 rb = rr[1];
                acc2[p] = fma2(ra.x, wx, acc2[p]);
                acc2[p] = fma2(ra.y, wy, acc2[p]);
                acc2[p] = fma2(rb.x, wz, acc2[p]);
                acc2[p] = fma2(rb.y, ww2, acc2[p]);
            }
        }
        __syncwarp();   // done reading rp before next group reuses sP

        // ---- head: relu(tanh) -> Wout dot + bout, scattered per-bt stores ----
        #pragma unroll
        for (int p = 0; p < 8; p++) {
            float t0, t1; upk2(acc2[p], t0, t1);
            float u0 = fmaxf(ftanh(t0), 0.f);
            float u1 = fmaxf(ftanh(t1), 0.f);
            ull pu = pk2(wo * u0, wo * u1);
            #pragma unroll
            for (int off = 16; off > 0; off >>= 1)
                pu = add2(pu, __shfl_xor_sync(0xffffffffu, pu, off));
            if (lane == 0) {
                float s0, s1; upk2(pu, s0, s1);
                out[(size_t)(bt0v + 2 * p)     * NN + n] = s0 + bo;
                out[(size_t)(bt0v + 2 * p + 1) * NN + n] = s1 + bo;
            }
        }
    }
}

extern "C" void kernel_launch(void* const* d_in, const int* in_sizes, int n_in,
                              void* d_out, int out_size) {
    const float* X      = (const float*)d_in[0];
    const float* adj    = (const float*)d_in[1];
    const float* adjm   = (const float*)d_in[2];
    const float* Theta0 = (const float*)d_in[3];
    const float* bias0  = (const float*)d_in[4];
    const float* Wt0    = (const float*)d_in[5];
    const float* bt0    = (const float*)d_in[6];
    const float* Theta1 = (const float*)d_in[7];
    const float* bias1  = (const float*)d_in[8];
    const float* Wt1    = (const float*)d_in[9];
    const float* bt1    = (const float*)d_in[10];
    const float* Wout   = (const float*)d_in[11];
    const float* bout   = (const float*)d_in[12];
    float* out = (float*)d_out;

    prep_kernel<<<5, 256>>>(Theta1, Wt1);
    topk_kernel<<<(2 * NN * 32 + 255) / 256, 256>>>(adj, adjm);
    stage1_kernel<<<750, 256>>>(X, Theta0, bias0, Wt0, bt0);
    stage2_kernel<<<(NG2 + 3) / 4, 128>>>(bias1, bt1, Wout, bout, out);
}

// round 7
// speedup vs baseline: 2.3101x; 1.0032x over previous
#include <cuda_runtime.h>
#include <math.h>

#define Bb 4
#define Tt 12
#define NN 2000
#define KK 8
#define KMAX 16
#define CC 32
#define TOT (Bb*Tt*NN)
#define UU1 4
#define NG1 (TOT/UU1)        // 24000 (stage1)
#define TB  16               // bt per stage2 group
#define CH  8                // phase-A chunk (register blocking)
#define NTB (Bb*Tt/TB)       // 3 bt-blocks
#define NG2 (NN*NTB)         // 6000 stage2 groups

// ---- scratch (no allocations allowed) ----
__device__ float2 g_nwi[2][NN][KMAX];  // (weight, idx-as-bits)
__device__ int    g_M[2][NN];          // stored entries (<=15)
__device__ int    g_cnt[2][NN];        // true kept count
__device__ float  g_inv[2][NN];        // 1/deg
__device__ float  g_h1[(size_t)TOT * CC];
__device__ float4 g_Te3[CC * CC];      // folded Theta1 (s=log1p(8)): [f*32+o] = {q0..q3}
__device__ float4 g_TeA[CC * CC];      // Theta1 block A vectorized
__device__ float4 g_TeB[CC * CC];      // block B
__device__ float4 g_TeC[CC * CC];      // block C
__device__ float4 g_Wt1v[8 * CC];      // Wt1 vectorized: [q*32+o] = Wt1[o][4q..4q+3]

typedef unsigned long long ull;

__device__ __forceinline__ float maskf(float v) {
    if (isnan(v)) v = 6.0f;
    if (isinf(v)) v = 0.0f;
    return fminf(v, 6.0f);
}
__device__ __forceinline__ float ftanh(float x) {
    float e = __expf(2.0f * x);
    return 1.0f - __fdividef(2.0f, e + 1.0f);
}
__device__ __forceinline__ ull pk2(float a, float b) {
    ull r; asm("mov.b64 %0, {%1,%2};" : "=l"(r) : "f"(a), "f"(b)); return r;
}
__device__ __forceinline__ void upk2(ull v, float& a, float& b) {
    asm("mov.b64 {%0,%1}, %2;" : "=f"(a), "=f"(b) : "l"(v));
}
__device__ __forceinline__ ull fma2(ull a, ull b, ull c) {
    ull d; asm("fma.rn.f32x2 %0, %1, %2, %3;" : "=l"(d) : "l"(a), "l"(b), "l"(c)); return d;
}
__device__ __forceinline__ ull add2(ull a, ull b) {
    ull d; asm("add.rn.f32x2 %0, %1, %2;" : "=l"(d) : "l"(a), "l"(b)); return d;
}

// ---------------- top-K: warp per row (exact tie semantics) ----------------
__global__ void __launch_bounds__(256) topk_kernel(const float* __restrict__ adj,
                                                   const float* __restrict__ adjm) {
    int gw = (blockIdx.x * 256 + threadIdx.x) >> 5;
    if (gw >= 2 * NN) return;
    int mat = gw / NN;
    int row = gw - mat * NN;
    const float4* src4 = (const float4*)((mat == 0 ? adj : adjm) + (size_t)row * NN);
    int lane = threadIdx.x & 31;
    unsigned lt = (1u << lane) - 1u;

    float v0=-INFINITY,v1=-INFINITY,v2=-INFINITY,v3=-INFINITY,
          v4=-INFINITY,v5=-INFINITY,v6=-INFINITY,v7=-INFINITY;

    #define INS(xx) do { float x_ = (xx); \
        v7 = fmaxf(v7, fminf(v6, x_)); \
        v6 = fmaxf(v6, fminf(v5, x_)); \
        v5 = fmaxf(v5, fminf(v4, x_)); \
        v4 = fmaxf(v4, fminf(v3, x_)); \
        v3 = fmaxf(v3, fminf(v2, x_)); \
        v2 = fmaxf(v2, fminf(v1, x_)); \
        v1 = fmaxf(v1, fminf(v0, x_)); \
        v0 = fmaxf(v0, x_); } while(0)

    #pragma unroll 4
    for (int t = 0; t < 16; t++) {
        int i4 = lane + t * 32;
        if (i4 < 500) {
            float4 f = __ldg(&src4[i4]);
            INS(f.x); INS(f.y); INS(f.z); INS(f.w);
        }
    }
    #undef INS

    float thr = -INFINITY;
    #pragma unroll
    for (int k = 0; k < 8; k++) {
        float cv = v0; int cl = lane;
        #pragma unroll
        for (int off = 16; off > 0; off >>= 1) {
            float ov = __shfl_xor_sync(0xffffffffu, cv, off);
            int   ol = __shfl_xor_sync(0xffffffffu, cl, off);
            if (ov > cv || (ov == cv && ol < cl)) { cv = ov; cl = ol; }
        }
        if (cl == lane) { v0=v1; v1=v2; v2=v3; v3=v4; v4=v5; v5=v6; v6=v7; v7=-INFINITY; }
        thr = cv;
    }

    int cgt = 0, ceq = 0;
    float sgt = 0.f;
    for (int t = 0; t < 16; t++) {
        int i4 = lane + t * 32;
        float4 f;
        if (i4 < 500) f = __ldg(&src4[i4]);
        else { f.x=f.y=f.z=f.w=-INFINITY; }
        bool any = (f.x >= thr) | (f.y >= thr) | (f.z >= thr) | (f.w >= thr);
        if (__ballot_sync(0xffffffffu, any) == 0u) continue;
        int ib = 4 * i4;
        #pragma unroll
        for (int s = 0; s < 4; s++) {
            float x = (s==0)?f.x:(s==1)?f.y:(s==2)?f.z:f.w;
            int   i = ib + s;
            bool gt = x >  thr;
            bool ge = x >= thr;
            unsigned mgt = __ballot_sync(0xffffffffu, gt);
            unsigned mge = __ballot_sync(0xffffffffu, ge);
            unsigned meq = mge & ~mgt;
            if (gt) {
                int p = cgt + __popc(mgt & lt);
                g_nwi[mat][row][p] = make_float2(x, __int_as_float(i));
                sgt += x;
            }
            cgt += __popc(mgt);
            if (meq) {
                if (ge && !gt) {
                    int p = ceq + __popc(meq & lt);
                    if (p < 8) g_nwi[mat][row][8 + p] = make_float2(x, __int_as_float(i));
                }
                ceq += __popc(meq);
            }
        }
    }
    #pragma unroll
    for (int off = 16; off > 0; off >>= 1)
        sgt += __shfl_xor_sync(0xffffffffu, sgt, off);

    if (lane == 0) {
        int cnt = cgt + ceq;
        int eq_stored = ceq < 8 ? ceq : 8;
        int M = cgt + eq_stored;
        for (int e = 0; e < eq_stored; e++)
            g_nwi[mat][row][cgt + e] = g_nwi[mat][row][8 + e];
        g_M[mat][row]   = M;
        g_cnt[mat][row] = cnt;
        g_inv[mat][row] = 1.0f / (sgt + (float)ceq * thr);
    }
}

// ---------------- prep: fold + vectorize weights ----------------
__global__ void __launch_bounds__(256) prep_kernel(const float* __restrict__ Theta1,
                                                   const float* __restrict__ Wt1) {
    int idx = blockIdx.x * 256 + threadIdx.x;
    if (idx < CC * CC) {
        int f = idx >> 5, o = idx & 31;
        const float s8  = log1pf(8.0f);
        const float is8 = 1.0f / s8;
        float4 va, vb, vc, ve;
        float *pa=(float*)&va, *pb=(float*)&vb, *pc=(float*)&vc, *pe=(float*)&ve;
        #pragma unroll
        for (int q = 0; q < 4; q++) {
            int src = (q * CC + f) * CC + o;
            float A = Theta1[src];
            float B = Theta1[4*CC*CC + src];
            float C = Theta1[8*CC*CC + src];
            pa[q] = A; pb[q] = B; pc[q] = C;
            pe[q] = A + s8 * B + is8 * C;
        }
        g_TeA[idx] = va; g_TeB[idx] = vb; g_TeC[idx] = vc; g_Te3[idx] = ve;
    } else if (idx < CC * CC + 8 * CC) {
        int i = idx - CC * CC;
        int q = i >> 5, o = i & 31;
        g_Wt1v[i] = ((const float4*)Wt1)[o * 8 + q];
    }
}

// ---------------- stage 1: stower0 (masking) + tcn0 ----------------
__global__ void __launch_bounds__(256) stage1_kernel(const float* __restrict__ X,
                              const float* __restrict__ Theta0,
                              const float* __restrict__ bias0,
                              const float* __restrict__ Wt0,
                              const float* __restrict__ bt0) {
    __shared__ float4 sR[8][UU1][8];
    int tid = threadIdx.x;
    int lane = tid & 31;
    int w    = tid >> 5;

    float t0a = __ldg(&Theta0[lane]),      t0b = __ldg(&Theta0[CC + lane]);
    float t0c = __ldg(&Theta0[2*CC+lane]), t0d = __ldg(&Theta0[3*CC + lane]);
    float b0 = __ldg(&bias0[lane]), btc = __ldg(&bt0[lane]);
    float4 wv[8];
    #pragma unroll
    for (int q = 0; q < 8; q++) wv[q] = __ldg(&((const float4*)Wt0)[lane * 8 + q]);

    int warpId = blockIdx.x * 8 + w;
    int nW = gridDim.x * 8;

    for (int grp = warpId; grp < NG1; grp += nW) {
        int g0 = grp * UU1;
        float o_u[UU1];
        #pragma unroll
        for (int u = 0; u < UU1; u++) {
            int g = g0 + u;
            int n = g % NN, bt = g / NN;
            int M = g_M[1][n];
            float inv = g_inv[1][n];
            float wt = 0.f, xv = 0.f;
            if (lane < M) {
                float2 wi = g_nwi[1][n][lane];
                wt = wi.x;
                xv = X[bt * NN + __float_as_int(wi.y)];
            }
            float t = wt * xv;
            float sw = t, sw2 = t * xv;
            bool vld = (lane < KK) && (wt > 0.f);
            float mx = vld ? xv : -INFINITY;
            float mn = vld ? xv : INFINITY;
            #pragma unroll
            for (int off = 16; off > 0; off >>= 1) {
                sw  += __shfl_xor_sync(0xffffffffu, sw,  off);
                sw2 += __shfl_xor_sync(0xffffffffu, sw2, off);
                mx = fmaxf(mx, __shfl_xor_sync(0xffffffffu, mx, off));
                mn = fminf(mn, __shfl_xor_sync(0xffffffffu, mn, off));
            }
            float mean = sw * inv;
            float sd   = sqrtf(fmaxf(sw2 * inv - mean * mean, 0.f) + 1e-5f);
            mean = maskf(mean); mx = maskf(mx); mn = maskf(mn); sd = maskf(sd);
            float o = b0 + mean * t0a + mx * t0b + mn * t0c + sd * t0d;
            o_u[u] = o;
            ((float*)&sR[w][u][0])[lane] = o;
        }
        __syncwarp();
        float acc[UU1];
        #pragma unroll
        for (int u = 0; u < UU1; u++) acc[u] = btc + o_u[u];
        #pragma unroll
        for (int q = 0; q < 8; q++) {
            #pragma unroll
            for (int u = 0; u < UU1; u++) {
                float4 r = sR[w][u][q];
                acc[u] += wv[q].x * r.x + wv[q].y * r.y + wv[q].z * r.z + wv[q].w * r.w;
            }
        }
        __syncwarp();
        #pragma unroll
        for (int u = 0; u < UU1; u++)
            g_h1[(size_t)(g0 + u) * CC + lane] = ftanh(acc[u]);
    }
}

// ---------------- stage 2: n-major, 16 bt/warp, chunked phase A -------------
__global__ void __launch_bounds__(128) stage2_kernel(const float* __restrict__ bias1,
                              const float* __restrict__ bt1,
                              const float* __restrict__ Wout,
                              const float* __restrict__ bout,
                              float* __restrict__ out) {
    __shared__ float4 sP[4][8][2][CC];   // 32 KB: [warp][pair][half][f]
    int tid = threadIdx.x;
    int lane = tid & 31;
    int w    = tid >> 5;

    float b1 = __ldg(&bias1[lane]), btc = __ldg(&bt1[lane]);
    float wo = __ldg(&Wout[lane]),  bo  = __ldg(&bout[0]);

    int warpId = blockIdx.x * 4 + w;
    int nW = gridDim.x * 4;

    for (int grp = warpId; grp < NG2; grp += nW) {
        int n  = grp / NTB;
        int tb = grp - n * NTB;
        int bt0v = tb * TB;

        int M   = g_M[0][n];
        int cnt = g_cnt[0][n];
        float inv = g_inv[0][n];
        bool fast = (cnt == KK);

        float wreg = 0.f; int ireg = 0;
        if (lane < M) {
            float2 wi = g_nwi[0][n][lane];
            wreg = wi.x; ireg = __float_as_int(wi.y);
        }

        // ---- phase A: stats in 2 chunks of 8 bt (register blocking) ----
        #pragma unroll
        for (int ch = 0; ch < 2; ch++) {
            float sw[CH], sw2[CH], mxv[CH], mnv[CH];
            #pragma unroll
            for (int u = 0; u < CH; u++) {
                sw[u] = 0.f; sw2[u] = 0.f; mxv[u] = -INFINITY; mnv[u] = INFINITY;
            }
            size_t cbase = (size_t)(bt0v + ch * CH) * NN * CC + lane;
            for (int j = 0; j < M; j++) {
                float wtj = __shfl_sync(0xffffffffu, wreg, j);
                int   mij = __shfl_sync(0xffffffffu, ireg, j);
                const float* hp = g_h1 + cbase + (size_t)mij * CC;
                bool pos = (j < KK) && (wtj > 0.f);
                if (pos) {
                    #pragma unroll
                    for (int u = 0; u < CH; u++) {
                        float hv = __ldg(hp + (size_t)u * (NN * CC));
                        float t = wtj * hv;
                        sw[u] += t; sw2[u] += t * hv;
                        mxv[u] = fmaxf(mxv[u], hv); mnv[u] = fminf(mnv[u], hv);
                    }
                } else {
                    #pragma unroll
                    for (int u = 0; u < CH; u++) {
                        float hv = __ldg(hp + (size_t)u * (NN * CC));
                        float t = wtj * hv;
                        sw[u] += t; sw2[u] += t * hv;
                    }
                }
            }
            #pragma unroll
            for (int u = 0; u < CH; u++) {
                float mean = sw[u] * inv;
                float sd = sqrtf(fmaxf(sw2[u] * inv - mean * mean, 0.f) + 1e-5f);
                sw[u] = mean; sw2[u] = sd;
            }
            #pragma unroll
            for (int p = 0; p < CH / 2; p++) {
                int u0 = 2 * p, u1 = 2 * p + 1;
                int gp = ch * (CH / 2) + p;
                sP[w][gp][0][lane] = make_float4(sw[u0], sw[u1], mxv[u0], mxv[u1]);
                sP[w][gp][1][lane] = make_float4(mnv[u0], mnv[u1], sw2[u0], sw2[u1]);
            }
        }
        __syncwarp();

        // ---- phase B: Theta matmul (f32x2) ----
        ull acc[8];
        #pragma unroll
        for (int p = 0; p < 8; p++) acc[p] = pk2(b1, b1);

        if (fast) {
            #pragma unroll 2
            for (int f = 0; f < CC; f++) {
                float4 wv = __ldg(&g_Te3[f * CC + lane]);
                ull wx = pk2(wv.x, wv.x), wy = pk2(wv.y, wv.y);
                ull wz = pk2(wv.z, wv.z), ww2 = pk2(wv.w, wv.w);
                #pragma unroll
                for (int p = 0; p < 8; p++) {
                    ulonglong2 a = *(const ulonglong2*)&sP[w][p][0][f];
                    ulonglong2 b = *(const ulonglong2*)&sP[w][p][1][f];
                    acc[p] = fma2(a.x, wx, acc[p]);
                    acc[p] = fma2(a.y, wy, acc[p]);
                    acc[p] = fma2(b.x, wz, acc[p]);
                    acc[p] = fma2(b.y, ww2, acc[p]);
                }
            }
        } else {   // ties: s = log1p(cnt) uniform per n; fold on the fly
            float s  = log1pf((float)cnt);
            float is = 1.0f / s;
            for (int f = 0; f < CC; f++) {
                float4 a4 = __ldg(&g_TeA[f * CC + lane]);
                float4 b4 = __ldg(&g_TeB[f * CC + lane]);
                float4 c4 = __ldg(&g_TeC[f * CC + lane]);
                float4 wv;
                wv.x = a4.x + s * b4.x + is * c4.x;
                wv.y = a4.y + s * b4.y + is * c4.y;
                wv.z = a4.z + s * b4.z + is * c4.z;
                wv.w = a4.w + s * b4.w + is * c4.w;
                ull wx = pk2(wv.x, wv.x), wy = pk2(wv.y, wv.y);
                ull wz = pk2(wv.z, wv.z), ww2 = pk2(wv.w, wv.w);
                #pragma unroll
                for (int p = 0; p < 8; p++) {
                    ulonglong2 a = *(const ulonglong2*)&sP[w][p][0][f];
                    ulonglong2 b = *(const ulonglong2*)&sP[w][p][1][f];
                    acc[p] = fma2(a.x, wx, acc[p]);
                    acc[p] = fma2(a.y, wy, acc[p]);
                    acc[p] = fma2(b.x, wz, acc[p]);
                    acc[p] = fma2(b.y, ww2, acc[p]);
                }
            }
        }
        __syncwarp();

        // ---- phase C: relu -> tcn1 (f32x2) ----
        float2* rp = (float2*)&sP[w][0][0][0];
        ull racc[8];
        #pragma unroll
        for (int p = 0; p < 8; p++) {
            float a0, a1; upk2(acc[p], a0, a1);
            float r0 = fmaxf(a0, 0.f), r1 = fmaxf(a1, 0.f);
            rp[p * 32 + lane] = make_float2(r0, r1);
            racc[p] = pk2(r0, r1);
        }
        __syncwarp();

        ull acc2[8];
        ull btc2 = pk2(btc, btc);
        #pragma unroll
        for (int p = 0; p < 8; p++) acc2[p] = add2(btc2, racc[p]);
        #pragma unroll
        for (int q = 0; q < 8; q++) {
            float4 wq = __ldg(&g_Wt1v[q * CC + lane]);
            ull wx = pk2(wq.x, wq.x), wy = pk2(wq.y, wq.y);
            ull wz = pk2(wq.z, wq.z), ww2 = pk2(wq.w, wq.w);
            #pragma unroll
            for (int p = 0; p < 8; p++) {
                const ulonglong2* rr = (const ulonglong2*)&rp[p * 32 + 4 * q];
                ulonglong2 ra = rr[0];
                ulonglong2 rb = rr[1];
                acc2[p] = fma2(ra.x, wx, acc2[p]);
                acc2[p] = fma2(ra.y, wy, acc2[p]);
                acc2[p] = fma2(rb.x, wz, acc2[p]);
                acc2[p] = fma2(rb.y, ww2, acc2[p]);
            }
        }
        __syncwarp();

        // ---- head ----
        #pragma unroll
        for (int p = 0; p < 8; p++) {
            float t0, t1; upk2(acc2[p], t0, t1);
            float u0 = fmaxf(ftanh(t0), 0.f);
            float u1 = fmaxf(ftanh(t1), 0.f);
            ull pu = pk2(wo * u0, wo * u1);
            #pragma unroll
            for (int off = 16; off > 0; off >>= 1)
                pu = add2(pu, __shfl_xor_sync(0xffffffffu, pu, off));
            if (lane == 0) {
                float s0, s1; upk2(pu, s0, s1);
                out[(size_t)(bt0v + 2 * p)     * NN + n] = s0 + bo;
                out[(size_t)(bt0v + 2 * p + 1) * NN + n] = s1 + bo;
            }
        }
    }
}

extern "C" void kernel_launch(void* const* d_in, const int* in_sizes, int n_in,
                              void* d_out, int out_size) {
    const float* X      = (const float*)d_in[0];
    const float* adj    = (const float*)d_in[1];
    const float* adjm   = (const float*)d_in[2];
    const float* Theta0 = (const float*)d_in[3];
    const float* bias0  = (const float*)d_in[4];
    const float* Wt0    = (const float*)d_in[5];
    const float* bt0    = (const float*)d_in[6];
    const float* Theta1 = (const float*)d_in[7];
    const float* bias1  = (const float*)d_in[8];
    const float* Wt1    = (const float*)d_in[9];
    const float* bt1    = (const float*)d_in[10];
    const float* Wout   = (const float*)d_in[11];
    const float* bout   = (const float*)d_in[12];
    float* out = (float*)d_out;

    prep_kernel<<<5, 256>>>(Theta1, Wt1);
    topk_kernel<<<(2 * NN * 32 + 255) / 256, 256>>>(adj, adjm);
    stage1_kernel<<<750, 256>>>(X, Theta0, bias0, Wt0, bt0);
    stage2_kernel<<<(NG2 + 3) / 4, 128>>>(bias1, bt1, Wout, bout, out);
}

// round 8
// speedup vs baseline: 2.9653x; 1.2836x over previous
#include <cuda_runtime.h>
#include <math.h>

#define Bb 4
#define Tt 12
#define NN 2000
#define KK 8
#define KMAX 16
#define CC 32
#define NBT (Bb*Tt)          // 48
#define TOT (Bb*Tt*NN)
#define TB  16               // bt per stage2 group
#define CH  8                // stage2 phase-A chunk
#define NTB (NBT/TB)         // 3
#define NG2 (NN*NTB)         // 6000 stage2 groups

// ---- scratch (no allocations allowed) ----
__device__ float2 g_nwi[2][NN][KMAX];  // (weight, idx-as-bits)
__device__ int    g_M[2][NN];          // stored entries (<=15)
__device__ int    g_cnt[2][NN];        // true kept count
__device__ float  g_inv[2][NN];        // 1/deg
__device__ float  g_h1[(size_t)TOT * CC];
__device__ float  g_XT[NN * NBT];      // X transposed: [n][bt]
__device__ float4 g_Te3[CC * CC];      // folded Theta1 (s=log1p(8)): [f*32+o]={q0..q3}
__device__ float4 g_TeA[CC * CC];      // Theta1 block A
__device__ float4 g_TeB[CC * CC];      // block B
__device__ float4 g_TeC[CC * CC];      // block C
__device__ float4 g_Wt1v[8 * CC];      // Wt1: [q*32+o] = Wt1[o][4q..4q+3]

typedef unsigned long long ull;

__device__ __forceinline__ float maskf(float v) {
    if (isnan(v)) v = 6.0f;
    if (isinf(v)) v = 0.0f;
    return fminf(v, 6.0f);
}
__device__ __forceinline__ float ftanh(float x) {
    float e = __expf(2.0f * x);
    return 1.0f - __fdividef(2.0f, e + 1.0f);
}
__device__ __forceinline__ ull pk2(float a, float b) {
    ull r; asm("mov.b64 %0, {%1,%2};" : "=l"(r) : "f"(a), "f"(b)); return r;
}
__device__ __forceinline__ void upk2(ull v, float& a, float& b) {
    asm("mov.b64 {%0,%1}, %2;" : "=f"(a), "=f"(b) : "l"(v));
}
__device__ __forceinline__ ull fma2(ull a, ull b, ull c) {
    ull d; asm("fma.rn.f32x2 %0, %1, %2, %3;" : "=l"(d) : "l"(a), "l"(b), "l"(c)); return d;
}
__device__ __forceinline__ ull add2(ull a, ull b) {
    ull d; asm("add.rn.f32x2 %0, %1, %2;" : "=l"(d) : "l"(a), "l"(b)); return d;
}

// ================= setup: topk (blocks 0-499) + prep (500-504) + XT (505-879)
__global__ void __launch_bounds__(256) setup_kernel(const float* __restrict__ adj,
                                                    const float* __restrict__ adjm,
                                                    const float* __restrict__ Theta1,
                                                    const float* __restrict__ Wt1,
                                                    const float* __restrict__ X) {
    int b = blockIdx.x;
    int tid = threadIdx.x;
    if (b >= 505) {                       // ---- X transpose ----
        int idx = (b - 505) * 256 + tid;  // idx = n*48 + bt
        g_XT[idx] = X[(idx % NBT) * NN + idx / NBT];
        return;
    }
    if (b >= 500) {                       // ---- weight prep ----
        int idx = (b - 500) * 256 + tid;
        if (idx < CC * CC) {
            int f = idx >> 5, o = idx & 31;
            const float s8  = log1pf(8.0f);
            const float is8 = 1.0f / s8;
            float4 va, vb, vc, ve;
            float *pa=(float*)&va, *pb=(float*)&vb, *pc=(float*)&vc, *pe=(float*)&ve;
            #pragma unroll
            for (int q = 0; q < 4; q++) {
                int src = (q * CC + f) * CC + o;
                float A = Theta1[src];
                float B = Theta1[4*CC*CC + src];
                float C = Theta1[8*CC*CC + src];
                pa[q] = A; pb[q] = B; pc[q] = C;
                pe[q] = A + s8 * B + is8 * C;
            }
            g_TeA[idx] = va; g_TeB[idx] = vb; g_TeC[idx] = vc; g_Te3[idx] = ve;
        } else if (idx < CC * CC + 8 * CC) {
            int i = idx - CC * CC;
            int q = i >> 5, o = i & 31;
            g_Wt1v[i] = ((const float4*)Wt1)[o * 8 + q];
        }
        return;
    }
    // ---- top-K: warp per row (exact tie semantics) ----
    int gw = b * 8 + (tid >> 5);
    int mat = gw / NN;
    int row = gw - mat * NN;
    const float4* src4 = (const float4*)((mat == 0 ? adj : adjm) + (size_t)row * NN);
    int lane = tid & 31;
    unsigned lt = (1u << lane) - 1u;

    float v0=-INFINITY,v1=-INFINITY,v2=-INFINITY,v3=-INFINITY,
          v4=-INFINITY,v5=-INFINITY,v6=-INFINITY,v7=-INFINITY;

    #define INS(xx) do { float x_ = (xx); \
        v7 = fmaxf(v7, fminf(v6, x_)); \
        v6 = fmaxf(v6, fminf(v5, x_)); \
        v5 = fmaxf(v5, fminf(v4, x_)); \
        v4 = fmaxf(v4, fminf(v3, x_)); \
        v3 = fmaxf(v3, fminf(v2, x_)); \
        v2 = fmaxf(v2, fminf(v1, x_)); \
        v1 = fmaxf(v1, fminf(v0, x_)); \
        v0 = fmaxf(v0, x_); } while(0)

    #pragma unroll 4
    for (int t = 0; t < 16; t++) {
        int i4 = lane + t * 32;
        if (i4 < 500) {
            float4 f = __ldg(&src4[i4]);
            INS(f.x); INS(f.y); INS(f.z); INS(f.w);
        }
    }
    #undef INS

    float thr = -INFINITY;
    #pragma unroll
    for (int k = 0; k < 8; k++) {
        float cv = v0; int cl = lane;
        #pragma unroll
        for (int off = 16; off > 0; off >>= 1) {
            float ov = __shfl_xor_sync(0xffffffffu, cv, off);
            int   ol = __shfl_xor_sync(0xffffffffu, cl, off);
            if (ov > cv || (ov == cv && ol < cl)) { cv = ov; cl = ol; }
        }
        if (cl == lane) { v0=v1; v1=v2; v2=v3; v3=v4; v4=v5; v5=v6; v6=v7; v7=-INFINITY; }
        thr = cv;
    }

    int cgt = 0, ceq = 0;
    float sgt = 0.f;
    for (int t = 0; t < 16; t++) {
        int i4 = lane + t * 32;
        float4 f;
        if (i4 < 500) f = __ldg(&src4[i4]);
        else { f.x=f.y=f.z=f.w=-INFINITY; }
        bool any = (f.x >= thr) | (f.y >= thr) | (f.z >= thr) | (f.w >= thr);
        if (__ballot_sync(0xffffffffu, any) == 0u) continue;
        int ib = 4 * i4;
        #pragma unroll
        for (int s = 0; s < 4; s++) {
            float x = (s==0)?f.x:(s==1)?f.y:(s==2)?f.z:f.w;
            int   i = ib + s;
            bool gt = x >  thr;
            bool ge = x >= thr;
            unsigned mgt = __ballot_sync(0xffffffffu, gt);
            unsigned mge = __ballot_sync(0xffffffffu, ge);
            unsigned meq = mge & ~mgt;
            if (gt) {
                int p = cgt + __popc(mgt & lt);
                g_nwi[mat][row][p] = make_float2(x, __int_as_float(i));
                sgt += x;
            }
            cgt += __popc(mgt);
            if (meq) {
                if (ge && !gt) {
                    int p = ceq + __popc(meq & lt);
                    if (p < 8) g_nwi[mat][row][8 + p] = make_float2(x, __int_as_float(i));
                }
                ceq += __popc(meq);
            }
        }
    }
    #pragma unroll
    for (int off = 16; off > 0; off >>= 1)
        sgt += __shfl_xor_sync(0xffffffffu, sgt, off);

    if (lane == 0) {
        int cnt = cgt + ceq;
        int eq_stored = ceq < 8 ? ceq : 8;
        int M = cgt + eq_stored;
        for (int e = 0; e < eq_stored; e++)
            g_nwi[mat][row][cgt + e] = g_nwi[mat][row][8 + e];
        g_M[mat][row]   = M;
        g_cnt[mat][row] = cnt;
        g_inv[mat][row] = 1.0f / (sgt + (float)ceq * thr);
    }
}

// ================= stage 1: n-major, warp = n x 48 bt, scalar stats =========
__global__ void __launch_bounds__(256) stage1_kernel(const float* __restrict__ Theta0,
                              const float* __restrict__ bias0,
                              const float* __restrict__ Wt0,
                              const float* __restrict__ bt0) {
    __shared__ float4 sStat[8][NBT];       // per-warp stats[bt] (masked)  6KB
    __shared__ float2 sR[8][8 * CC];       // per-warp pair staging        16KB
    int tid = threadIdx.x;
    int lane = tid & 31;
    int w    = tid >> 5;
    int n = blockIdx.x * 8 + w;            // 250*8 = 2000 exact

    float b0  = __ldg(&bias0[lane]), btc = __ldg(&bt0[lane]);
    ull t0m = pk2(__ldg(&Theta0[lane]),        __ldg(&Theta0[lane]));
    ull t0x = pk2(__ldg(&Theta0[CC+lane]),     __ldg(&Theta0[CC+lane]));
    ull t0n = pk2(__ldg(&Theta0[2*CC+lane]),   __ldg(&Theta0[2*CC+lane]));
    ull t0s = pk2(__ldg(&Theta0[3*CC+lane]),   __ldg(&Theta0[3*CC+lane]));
    float4 wv[8];
    #pragma unroll
    for (int q = 0; q < 8; q++) wv[q] = __ldg(&((const float4*)Wt0)[lane * 8 + q]);

    int M = g_M[1][n];
    float inv = g_inv[1][n];
    float wreg = 0.f; int ireg = 0;
    if (lane < M) {
        float2 wi = g_nwi[1][n][lane];
        wreg = wi.x; ireg = __float_as_int(wi.y);
    }

    // ---- phase A: scalar stats, lane = bt (u0: bt=lane, u1: bt=32+lane) ----
    float sw0=0.f, sq0=0.f, mx0=-INFINITY, mn0=INFINITY;
    float sw1=0.f, sq1=0.f, mx1=-INFINITY, mn1=INFINITY;
    if (M == KK) {
        #pragma unroll
        for (int j = 0; j < KK; j++) {
            float wtj = __shfl_sync(0xffffffffu, wreg, j);
            int   mij = __shfl_sync(0xffffffffu, ireg, j);
            const float* xp = g_XT + mij * NBT;
            float x0 = __ldg(xp + lane);
            float x1 = (lane < 16) ? __ldg(xp + 32 + lane) : 0.f;
            float t0 = wtj * x0, t1 = wtj * x1;
            sw0 += t0; sq0 += t0 * x0;
            sw1 += t1; sq1 += t1 * x1;
            if (wtj > 0.f) {
                mx0 = fmaxf(mx0, x0); mn0 = fminf(mn0, x0);
                mx1 = fmaxf(mx1, x1); mn1 = fminf(mn1, x1);
            }
        }
    } else {
        for (int j = 0; j < M; j++) {
            float wtj = __shfl_sync(0xffffffffu, wreg, j);
            int   mij = __shfl_sync(0xffffffffu, ireg, j);
            const float* xp = g_XT + mij * NBT;
            float x0 = __ldg(xp + lane);
            float x1 = (lane < 16) ? __ldg(xp + 32 + lane) : 0.f;
            float t0 = wtj * x0, t1 = wtj * x1;
            sw0 += t0; sq0 += t0 * x0;
            sw1 += t1; sq1 += t1 * x1;
            if (j < KK && wtj > 0.f) {
                mx0 = fmaxf(mx0, x0); mn0 = fminf(mn0, x0);
                mx1 = fmaxf(mx1, x1); mn1 = fminf(mn1, x1);
            }
        }
    }
    {
        float mean = sw0 * inv;
        float sd = sqrtf(fmaxf(sq0 * inv - mean * mean, 0.f) + 1e-5f);
        sStat[w][lane] = make_float4(maskf(mean), maskf(mx0), maskf(mn0), maskf(sd));
    }
    if (lane < 16) {
        float mean = sw1 * inv;
        float sd = sqrtf(fmaxf(sq1 * inv - mean * mean, 0.f) + 1e-5f);
        sStat[w][32 + lane] = make_float4(maskf(mean), maskf(mx1), maskf(mn1), maskf(sd));
    }
    __syncwarp();

    // ---- phases B+C per 16-bt sub-batch (8 pairs), lane = channel ----
    ull b02 = pk2(b0, b0), btc2 = pk2(btc, btc);
    #pragma unroll
    for (int s = 0; s < NTB; s++) {
        int base = s * TB;
        float2* rp = &sR[w][0];
        ull racc[8];
        #pragma unroll
        for (int p = 0; p < 8; p++) {
            float4 A = sStat[w][base + 2 * p];
            float4 B = sStat[w][base + 2 * p + 1];
            ull o2 = b02;
            o2 = fma2(pk2(A.x, B.x), t0m, o2);
            o2 = fma2(pk2(A.y, B.y), t0x, o2);
            o2 = fma2(pk2(A.z, B.z), t0n, o2);
            o2 = fma2(pk2(A.w, B.w), t0s, o2);
            float f0, f1; upk2(o2, f0, f1);
            rp[p * CC + lane] = make_float2(f0, f1);
            racc[p] = o2;
        }
        __syncwarp();
        ull acc2[8];
        #pragma unroll
        for (int p = 0; p < 8; p++) acc2[p] = add2(btc2, racc[p]);
        #pragma unroll
        for (int q = 0; q < 8; q++) {
            ull wx = pk2(wv[q].x, wv[q].x), wy = pk2(wv[q].y, wv[q].y);
            ull wz = pk2(wv[q].z, wv[q].z), ww2 = pk2(wv[q].w, wv[q].w);
            #pragma unroll
            for (int p = 0; p < 8; p++) {
                const ulonglong2* rr = (const ulonglong2*)&rp[p * CC + 4 * q];
                ulonglong2 ra = rr[0];
                ulonglong2 rb = rr[1];
                acc2[p] = fma2(ra.x, wx, acc2[p]);
                acc2[p] = fma2(ra.y, wy, acc2[p]);
                acc2[p] = fma2(rb.x, wz, acc2[p]);
                acc2[p] = fma2(rb.y, ww2, acc2[p]);
            }
        }
        #pragma unroll
        for (int p = 0; p < 8; p++) {
            float a0, a1; upk2(acc2[p], a0, a1);
            int bt = base + 2 * p;
            g_h1[((size_t)bt * NN + n) * CC + lane]       = ftanh(a0);
            g_h1[((size_t)(bt + 1) * NN + n) * CC + lane] = ftanh(a1);
        }
        __syncwarp();
    }
}

// ================= stage 2: n-major, 16 bt/warp, unrolled gather ============
__global__ void __launch_bounds__(128) stage2_kernel(const float* __restrict__ bias1,
                              const float* __restrict__ bt1,
                              const float* __restrict__ Wout,
                              const float* __restrict__ bout,
                              float* __restrict__ out) {
    __shared__ float4 sP[4][8][2][CC];   // 32 KB
    int tid = threadIdx.x;
    int lane = tid & 31;
    int w    = tid >> 5;

    float b1 = __ldg(&bias1[lane]), btc = __ldg(&bt1[lane]);
    float wo = __ldg(&Wout[lane]),  bo  = __ldg(&bout[0]);

    int grp = blockIdx.x * 4 + w;
    if (grp >= NG2) return;
    int n  = grp / NTB;
    int tb = grp - n * NTB;
    int bt0v = tb * TB;

    int M   = g_M[0][n];
    int cnt = g_cnt[0][n];
    float inv = g_inv[0][n];
    bool fast = (cnt == KK);

    float wreg = 0.f; int ireg = 0;
    if (lane < M) {
        float2 wi = g_nwi[0][n][lane];
        wreg = wi.x; ireg = __float_as_int(wi.y);
    }

    // ---- phase A: stats in 2 chunks of 8 bt ----
    if (M == KK) {
        float wj[KK]; int ij[KK];
        #pragma unroll
        for (int j = 0; j < KK; j++) {
            wj[j] = __shfl_sync(0xffffffffu, wreg, j);
            ij[j] = __shfl_sync(0xffffffffu, ireg, j);
        }
        #pragma unroll
        for (int ch = 0; ch < 2; ch++) {
            float sw[CH], sq[CH], mxv[CH], mnv[CH];
            #pragma unroll
            for (int u = 0; u < CH; u++) {
                sw[u] = 0.f; sq[u] = 0.f; mxv[u] = -INFINITY; mnv[u] = INFINITY;
            }
            size_t cbase = (size_t)(bt0v + ch * CH) * NN * CC + lane;
            #pragma unroll
            for (int j = 0; j < KK; j++) {
                const float* hp = g_h1 + cbase + (size_t)ij[j] * CC;
                float wtj = wj[j];
                bool pos = wtj > 0.f;
                #pragma unroll
                for (int u = 0; u < CH; u++) {
                    float hv = __ldg(hp + (size_t)u * (NN * CC));
                    float t = wtj * hv;
                    sw[u] += t; sq[u] += t * hv;
                    if (pos) { mxv[u] = fmaxf(mxv[u], hv); mnv[u] = fminf(mnv[u], hv); }
                }
            }
            #pragma unroll
            for (int u = 0; u < CH; u++) {
                float mean = sw[u] * inv;
                float sd = sqrtf(fmaxf(sq[u] * inv - mean * mean, 0.f) + 1e-5f);
                sw[u] = mean; sq[u] = sd;
            }
            #pragma unroll
            for (int p = 0; p < CH / 2; p++) {
                int u0 = 2 * p, u1 = 2 * p + 1;
                int gp = ch * (CH / 2) + p;
                sP[w][gp][0][lane] = make_float4(sw[u0], sw[u1], mxv[u0], mxv[u1]);
                sP[w][gp][1][lane] = make_float4(mnv[u0], mnv[u1], sq[u0], sq[u1]);
            }
        }
    } else {
        #pragma unroll
        for (int ch = 0; ch < 2; ch++) {
            float sw[CH], sq[CH], mxv[CH], mnv[CH];
            #pragma unroll
            for (int u = 0; u < CH; u++) {
                sw[u] = 0.f; sq[u] = 0.f; mxv[u] = -INFINITY; mnv[u] = INFINITY;
            }
            size_t cbase = (size_t)(bt0v + ch * CH) * NN * CC + lane;
            for (int j = 0; j < M; j++) {
                float wtj = __shfl_sync(0xffffffffu, wreg, j);
                int   mij = __shfl_sync(0xffffffffu, ireg, j);
                const float* hp = g_h1 + cbase + (size_t)mij * CC;
                bool pos = (j < KK) && (wtj > 0.f);
                #pragma unroll
                for (int u = 0; u < CH; u++) {
                    float hv = __ldg(hp + (size_t)u * (NN * CC));
                    float t = wtj * hv;
                    sw[u] += t; sq[u] += t * hv;
                    if (pos) { mxv[u] = fmaxf(mxv[u], hv); mnv[u] = fminf(mnv[u], hv); }
                }
            }
            #pragma unroll
            for (int u = 0; u < CH; u++) {
                float mean = sw[u] * inv;
                float sd = sqrtf(fmaxf(sq[u] * inv - mean * mean, 0.f) + 1e-5f);
                sw[u] = mean; sq[u] = sd;
            }
            #pragma unroll
            for (int p = 0; p < CH / 2; p++) {
                int u0 = 2 * p, u1 = 2 * p + 1;
                int gp = ch * (CH / 2) + p;
                sP[w][gp][0][lane] = make_float4(sw[u0], sw[u1], mxv[u0], mxv[u1]);
                sP[w][gp][1][lane] = make_float4(mnv[u0], mnv[u1], sq[u0], sq[u1]);
            }
        }
    }
    __syncwarp();

    // ---- phase B: Theta matmul (f32x2) ----
    ull acc[8];
    #pragma unroll
    for (int p = 0; p < 8; p++) acc[p] = pk2(b1, b1);

    if (fast) {
        #pragma unroll 2
        for (int f = 0; f < CC; f++) {
            float4 wv = __ldg(&g_Te3[f * CC + lane]);
            ull wx = pk2(wv.x, wv.x), wy = pk2(wv.y, wv.y);
            ull wz = pk2(wv.z, wv.z), ww2 = pk2(wv.w, wv.w);
            #pragma unroll
            for (int p = 0; p < 8; p++) {
                ulonglong2 a = *(const ulonglong2*)&sP[w][p][0][f];
                ulonglong2 b = *(const ulonglong2*)&sP[w][p][1][f];
                acc[p] = fma2(a.x, wx, acc[p]);
                acc[p] = fma2(a.y, wy, acc[p]);
                acc[p] = fma2(b.x, wz, acc[p]);
                acc[p] = fma2(b.y, ww2, acc[p]);
            }
        }
    } else {
        float s  = log1pf((float)cnt);
        float is = 1.0f / s;
        for (int f = 0; f < CC; f++) {
            float4 a4 = __ldg(&g_TeA[f * CC + lane]);
            float4 b4 = __ldg(&g_TeB[f * CC + lane]);
            float4 c4 = __ldg(&g_TeC[f * CC + lane]);
            float4 wv;
            wv.x = a4.x + s * b4.x + is * c4.x;
            wv.y = a4.y + s * b4.y + is * c4.y;
            wv.z = a4.z + s * b4.z + is * c4.z;
            wv.w = a4.w + s * b4.w + is * c4.w;
            ull wx = pk2(wv.x, wv.x), wy = pk2(wv.y, wv.y);
            ull wz = pk2(wv.z, wv.z), ww2 = pk2(wv.w, wv.w);
            #pragma unroll
            for (int p = 0; p < 8; p++) {
                ulonglong2 a = *(const ulonglong2*)&sP[w][p][0][f];
                ulonglong2 b = *(const ulonglong2*)&sP[w][p][1][f];
                acc[p] = fma2(a.x, wx, acc[p]);
                acc[p] = fma2(a.y, wy, acc[p]);
                acc[p] = fma2(b.x, wz, acc[p]);
                acc[p] = fma2(b.y, ww2, acc[p]);
            }
        }
    }
    __syncwarp();

    // ---- phase C: relu -> tcn1 (f32x2) ----
    float2* rp = (float2*)&sP[w][0][0][0];
    ull racc[8];
    #pragma unroll
    for (int p = 0; p < 8; p++) {
        float a0, a1; upk2(acc[p], a0, a1);
        float r0 = fmaxf(a0, 0.f), r1 = fmaxf(a1, 0.f);
        rp[p * 32 + lane] = make_float2(r0, r1);
        racc[p] = pk2(r0, r1);
    }
    __syncwarp();

    ull acc2[8];
    ull btc2 = pk2(btc, btc);
    #pragma unroll
    for (int p = 0; p < 8; p++) acc2[p] = add2(btc2, racc[p]);
    #pragma unroll
    for (int q = 0; q < 8; q++) {
        float4 wq = __ldg(&g_Wt1v[q * CC + lane]);
        ull wx = pk2(wq.x, wq.x), wy = pk2(wq.y, wq.y);
        ull wz = pk2(wq.z, wq.z), ww2 = pk2(wq.w, wq.w);
        #pragma unroll
        for (int p = 0; p < 8; p++) {
            const ulonglong2* rr = (const ulonglong2*)&rp[p * 32 + 4 * q];
            ulonglong2 ra = rr[0];
            ulonglong2 rb = rr[1];
            acc2[p] = fma2(ra.x, wx, acc2[p]);
            acc2[p] = fma2(ra.y, wy, acc2[p]);
            acc2[p] = fma2(rb.x, wz, acc2[p]);
            acc2[p] = fma2(rb.y, ww2, acc2[p]);
        }
    }

    // ---- head ----
    #pragma unroll
    for (int p = 0; p < 8; p++) {
        float t0, t1; upk2(acc2[p], t0, t1);
        float u0 = fmaxf(ftanh(t0), 0.f);
        float u1 = fmaxf(ftanh(t1), 0.f);
        ull pu = pk2(wo * u0, wo * u1);
        #pragma unroll
        for (int off = 16; off > 0; off >>= 1)
            pu = add2(pu, __shfl_xor_sync(0xffffffffu, pu, off));
        if (lane == 0) {
            float s0, s1; upk2(pu, s0, s1);
            out[(size_t)(bt0v + 2 * p)     * NN + n] = s0 + bo;
            out[(size_t)(bt0v + 2 * p + 1) * NN + n] = s1 + bo;
        }
    }
}

extern "C" void kernel_launch(void* const* d_in, const int* in_sizes, int n_in,
                              void* d_out, int out_size) {
    const float* X      = (const float*)d_in[0];
    const float* adj    = (const float*)d_in[1];
    const float* adjm   = (const float*)d_in[2];
    const float* Theta0 = (const float*)d_in[3];
    const float* bias0  = (const float*)d_in[4];
    const float* Wt0    = (const float*)d_in[5];
    const float* bt0    = (const float*)d_in[6];
    const float* Theta1 = (const float*)d_in[7];
    const float* bias1  = (const float*)d_in[8];
    const float* Wt1    = (const float*)d_in[9];
    const float* bt1    = (const float*)d_in[10];
    const float* Wout   = (const float*)d_in[11];
    const float* bout   = (const float*)d_in[12];
    float* out = (float*)d_out;

    setup_kernel<<<880, 256>>>(adj, adjm, Theta1, Wt1, X);
    stage1_kernel<<<250, 256>>>(Theta0, bias0, Wt0, bt0);
    stage2_kernel<<<(NG2 + 3) / 4, 128>>>(bias1, bt1, Wout, bout, out);
}

// round 9
// speedup vs baseline: 3.0334x; 1.0230x over previous
#include <cuda_runtime.h>
#include <math.h>

#define Bb 4
#define Tt 12
#define NN 2000
#define KK 8
#define KMAX 16
#define CC 32
#define NBT (Bb*Tt)          // 48
#define TOT (Bb*Tt*NN)
#define TB  16               // bt per stage2 group
#define CH  8                // stage2 chunk
#define NTB (NBT/TB)         // 3
#define NG2 (NN*NTB)         // 6000 stage2 groups

// ---- scratch (no allocations allowed) ----
__device__ float2 g_nwi[2][NN][KMAX];  // (weight, idx-as-bits)
__device__ int    g_M[2][NN];          // stored entries (<=15)
__device__ int    g_cnt[2][NN];        // true kept count
__device__ float  g_inv[2][NN];        // 1/deg
__device__ float  g_h1[(size_t)TOT * CC];
__device__ float  g_XT[NN * NBT];      // X transposed: [n][bt]
__device__ float4 g_Te3[CC * CC];      // folded Theta1 (s=log1p(8)): [f*32+o]={q0..q3}
__device__ float4 g_TeA[CC * CC];
__device__ float4 g_TeB[CC * CC];
__device__ float4 g_TeC[CC * CC];
__device__ float4 g_Wt1v[8 * CC];      // Wt1: [q*32+o] = Wt1[o][4q..4q+3]

typedef unsigned long long ull;

__device__ __forceinline__ float maskf(float v) {
    if (isnan(v)) v = 6.0f;
    if (isinf(v)) v = 0.0f;
    return fminf(v, 6.0f);
}
__device__ __forceinline__ float ftanh(float x) {
    float e = __expf(2.0f * x);
    return 1.0f - __fdividef(2.0f, e + 1.0f);
}
__device__ __forceinline__ ull pk2(float a, float b) {
    ull r; asm("mov.b64 %0, {%1,%2};" : "=l"(r) : "f"(a), "f"(b)); return r;
}
__device__ __forceinline__ void upk2(ull v, float& a, float& b) {
    asm("mov.b64 {%0,%1}, %2;" : "=f"(a), "=f"(b) : "l"(v));
}
__device__ __forceinline__ ull fma2(ull a, ull b, ull c) {
    ull d; asm("fma.rn.f32x2 %0, %1, %2, %3;" : "=l"(d) : "l"(a), "l"(b), "l"(c)); return d;
}
__device__ __forceinline__ ull add2(ull a, ull b) {
    ull d; asm("add.rn.f32x2 %0, %1, %2;" : "=l"(d) : "l"(a), "l"(b)); return d;
}

// ================= setup: topk (blocks 0-499) + prep (500-504) + XT (505-879)
__global__ void __launch_bounds__(256) setup_kernel(const float* __restrict__ adj,
                                                    const float* __restrict__ adjm,
                                                    const float* __restrict__ Theta1,
                                                    const float* __restrict__ Wt1,
                                                    const float* __restrict__ X) {
    int b = blockIdx.x;
    int tid = threadIdx.x;
    if (b >= 505) {                       // ---- X transpose ----
        int idx = (b - 505) * 256 + tid;  // idx = n*48 + bt
        g_XT[idx] = X[(idx % NBT) * NN + idx / NBT];
        return;
    }
    if (b >= 500) {                       // ---- weight prep ----
        int idx = (b - 500) * 256 + tid;
        if (idx < CC * CC) {
            int f = idx >> 5, o = idx & 31;
            const float s8  = log1pf(8.0f);
            const float is8 = 1.0f / s8;
            float4 va, vb, vc, ve;
            float *pa=(float*)&va, *pb=(float*)&vb, *pc=(float*)&vc, *pe=(float*)&ve;
            #pragma unroll
            for (int q = 0; q < 4; q++) {
                int src = (q * CC + f) * CC + o;
                float A = Theta1[src];
                float B = Theta1[4*CC*CC + src];
                float C = Theta1[8*CC*CC + src];
                pa[q] = A; pb[q] = B; pc[q] = C;
                pe[q] = A + s8 * B + is8 * C;
            }
            g_TeA[idx] = va; g_TeB[idx] = vb; g_TeC[idx] = vc; g_Te3[idx] = ve;
        } else if (idx < CC * CC + 8 * CC) {
            int i = idx - CC * CC;
            int q = i >> 5, o = i & 31;
            g_Wt1v[i] = ((const float4*)Wt1)[o * 8 + q];
        }
        return;
    }
    // ---- top-K: warp per row (exact tie semantics) ----
    int gw = b * 8 + (tid >> 5);
    int mat = gw / NN;
    int row = gw - mat * NN;
    const float4* src4 = (const float4*)((mat == 0 ? adj : adjm) + (size_t)row * NN);
    int lane = tid & 31;
    unsigned lt = (1u << lane) - 1u;

    float v0=-INFINITY,v1=-INFINITY,v2=-INFINITY,v3=-INFINITY,
          v4=-INFINITY,v5=-INFINITY,v6=-INFINITY,v7=-INFINITY;

    #define INS(xx) do { float x_ = (xx); \
        v7 = fmaxf(v7, fminf(v6, x_)); \
        v6 = fmaxf(v6, fminf(v5, x_)); \
        v5 = fmaxf(v5, fminf(v4, x_)); \
        v4 = fmaxf(v4, fminf(v3, x_)); \
        v3 = fmaxf(v3, fminf(v2, x_)); \
        v2 = fmaxf(v2, fminf(v1, x_)); \
        v1 = fmaxf(v1, fminf(v0, x_)); \
        v0 = fmaxf(v0, x_); } while(0)

    // pass 1a: cutoff-filtered insert (expected ~20 candidates/row)
    const float CUT = 0.99f;
    unsigned ccnt = 0;
    #pragma unroll 4
    for (int t = 0; t < 16; t++) {
        int i4 = lane + t * 32;
        float4 f;
        if (i4 < 500) f = __ldg(&src4[i4]);
        else { f.x=f.y=f.z=f.w=-INFINITY; }
        #pragma unroll
        for (int s = 0; s < 4; s++) {
            float x = (s==0)?f.x:(s==1)?f.y:(s==2)?f.z:f.w;
            bool cand = x > CUT;
            ccnt += cand;
            if (__any_sync(0xffffffffu, cand)) {
                if (cand) INS(x);
            }
        }
    }
    // verify enough candidates warp-wide; exact fallback otherwise
    unsigned total = __reduce_add_sync(0xffffffffu, ccnt);
    if (total < KK) {
        v0=v1=v2=v3=v4=v5=v6=v7 = -INFINITY;
        for (int t = 0; t < 16; t++) {
            int i4 = lane + t * 32;
            if (i4 < 500) {
                float4 f = __ldg(&src4[i4]);
                INS(f.x); INS(f.y); INS(f.z); INS(f.w);
            }
        }
    }
    #undef INS

    float thr = -INFINITY;
    #pragma unroll
    for (int k = 0; k < 8; k++) {
        float cv = v0; int cl = lane;
        #pragma unroll
        for (int off = 16; off > 0; off >>= 1) {
            float ov = __shfl_xor_sync(0xffffffffu, cv, off);
            int   ol = __shfl_xor_sync(0xffffffffu, cl, off);
            if (ov > cv || (ov == cv && ol < cl)) { cv = ov; cl = ol; }
        }
        if (cl == lane) { v0=v1; v1=v2; v2=v3; v3=v4; v4=v5; v5=v6; v6=v7; v7=-INFINITY; }
        thr = cv;
    }

    int cgt = 0, ceq = 0;
    float sgt = 0.f;
    for (int t = 0; t < 16; t++) {
        int i4 = lane + t * 32;
        float4 f;
        if (i4 < 500) f = __ldg(&src4[i4]);
        else { f.x=f.y=f.z=f.w=-INFINITY; }
        bool any = (f.x >= thr) | (f.y >= thr) | (f.z >= thr) | (f.w >= thr);
        if (__ballot_sync(0xffffffffu, any) == 0u) continue;
        int ib = 4 * i4;
        #pragma unroll
        for (int s = 0; s < 4; s++) {
            float x = (s==0)?f.x:(s==1)?f.y:(s==2)?f.z:f.w;
            int   i = ib + s;
            bool gt = x >  thr;
            bool ge = x >= thr;
            unsigned mgt = __ballot_sync(0xffffffffu, gt);
            unsigned mge = __ballot_sync(0xffffffffu, ge);
            unsigned meq = mge & ~mgt;
            if (gt) {
                int p = cgt + __popc(mgt & lt);
                g_nwi[mat][row][p] = make_float2(x, __int_as_float(i));
                sgt += x;
            }
            cgt += __popc(mgt);
            if (meq) {
                if (ge && !gt) {
                    int p = ceq + __popc(meq & lt);
                    if (p < 8) g_nwi[mat][row][8 + p] = make_float2(x, __int_as_float(i));
                }
                ceq += __popc(meq);
            }
        }
    }
    #pragma unroll
    for (int off = 16; off > 0; off >>= 1)
        sgt += __shfl_xor_sync(0xffffffffu, sgt, off);

    if (lane == 0) {
        int cnt = cgt + ceq;
        int eq_stored = ceq < 8 ? ceq : 8;
        int M = cgt + eq_stored;
        for (int e = 0; e < eq_stored; e++)
            g_nwi[mat][row][cgt + e] = g_nwi[mat][row][8 + e];
        g_M[mat][row]   = M;
        g_cnt[mat][row] = cnt;
        g_inv[mat][row] = 1.0f / (sgt + (float)ceq * thr);
    }
}

// ================= stage 1: n-major, warp = n x 48 bt, scalar stats =========
__global__ void __launch_bounds__(256) stage1_kernel(const float* __restrict__ Theta0,
                              const float* __restrict__ bias0,
                              const float* __restrict__ Wt0,
                              const float* __restrict__ bt0) {
    __shared__ float4 sStat[8][NBT];
    __shared__ float2 sR[8][8 * CC];
    int tid = threadIdx.x;
    int lane = tid & 31;
    int w    = tid >> 5;
    int n = blockIdx.x * 8 + w;

    float b0  = __ldg(&bias0[lane]), btc = __ldg(&bt0[lane]);
    ull t0m = pk2(__ldg(&Theta0[lane]),        __ldg(&Theta0[lane]));
    ull t0x = pk2(__ldg(&Theta0[CC+lane]),     __ldg(&Theta0[CC+lane]));
    ull t0n = pk2(__ldg(&Theta0[2*CC+lane]),   __ldg(&Theta0[2*CC+lane]));
    ull t0s = pk2(__ldg(&Theta0[3*CC+lane]),   __ldg(&Theta0[3*CC+lane]));
    float4 wv[8];
    #pragma unroll
    for (int q = 0; q < 8; q++) wv[q] = __ldg(&((const float4*)Wt0)[lane * 8 + q]);

    int M = g_M[1][n];
    float inv = g_inv[1][n];
    float wreg = 0.f; int ireg = 0;
    if (lane < M) {
        float2 wi = g_nwi[1][n][lane];
        wreg = wi.x; ireg = __float_as_int(wi.y);
    }

    float sw0=0.f, sq0=0.f, mx0=-INFINITY, mn0=INFINITY;
    float sw1=0.f, sq1=0.f, mx1=-INFINITY, mn1=INFINITY;
    if (M == KK) {
        #pragma unroll
        for (int j = 0; j < KK; j++) {
            float wtj = __shfl_sync(0xffffffffu, wreg, j);
            int   mij = __shfl_sync(0xffffffffu, ireg, j);
            const float* xp = g_XT + mij * NBT;
            float x0 = __ldg(xp + lane);
            float x1 = (lane < 16) ? __ldg(xp + 32 + lane) : 0.f;
            float t0 = wtj * x0, t1 = wtj * x1;
            sw0 += t0; sq0 += t0 * x0;
            sw1 += t1; sq1 += t1 * x1;
            if (wtj > 0.f) {
                mx0 = fmaxf(mx0, x0); mn0 = fminf(mn0, x0);
                mx1 = fmaxf(mx1, x1); mn1 = fminf(mn1, x1);
            }
        }
    } else {
        for (int j = 0; j < M; j++) {
            float wtj = __shfl_sync(0xffffffffu, wreg, j);
            int   mij = __shfl_sync(0xffffffffu, ireg, j);
            const float* xp = g_XT + mij * NBT;
            float x0 = __ldg(xp + lane);
            float x1 = (lane < 16) ? __ldg(xp + 32 + lane) : 0.f;
            float t0 = wtj * x0, t1 = wtj * x1;
            sw0 += t0; sq0 += t0 * x0;
            sw1 += t1; sq1 += t1 * x1;
            if (j < KK && wtj > 0.f) {
                mx0 = fmaxf(mx0, x0); mn0 = fminf(mn0, x0);
                mx1 = fmaxf(mx1, x1); mn1 = fminf(mn1, x1);
            }
        }
    }
    {
        float mean = sw0 * inv;
        float sd = sqrtf(fmaxf(sq0 * inv - mean * mean, 0.f) + 1e-5f);
        sStat[w][lane] = make_float4(maskf(mean), maskf(mx0), maskf(mn0), maskf(sd));
    }
    if (lane < 16) {
        float mean = sw1 * inv;
        float sd = sqrtf(fmaxf(sq1 * inv - mean * mean, 0.f) + 1e-5f);
        sStat[w][32 + lane] = make_float4(maskf(mean), maskf(mx1), maskf(mn1), maskf(sd));
    }
    __syncwarp();

    ull b02 = pk2(b0, b0), btc2 = pk2(btc, btc);
    #pragma unroll
    for (int s = 0; s < NTB; s++) {
        int base = s * TB;
        float2* rp = &sR[w][0];
        ull racc[8];
        #pragma unroll
        for (int p = 0; p < 8; p++) {
            float4 A = sStat[w][base + 2 * p];
            float4 B = sStat[w][base + 2 * p + 1];
            ull o2 = b02;
            o2 = fma2(pk2(A.x, B.x), t0m, o2);
            o2 = fma2(pk2(A.y, B.y), t0x, o2);
            o2 = fma2(pk2(A.z, B.z), t0n, o2);
            o2 = fma2(pk2(A.w, B.w), t0s, o2);
            float f0, f1; upk2(o2, f0, f1);
            rp[p * CC + lane] = make_float2(f0, f1);
            racc[p] = o2;
        }
        __syncwarp();
        ull acc2[8];
        #pragma unroll
        for (int p = 0; p < 8; p++) acc2[p] = add2(btc2, racc[p]);
        #pragma unroll
        for (int q = 0; q < 8; q++) {
            ull wx = pk2(wv[q].x, wv[q].x), wy = pk2(wv[q].y, wv[q].y);
            ull wz = pk2(wv[q].z, wv[q].z), ww2 = pk2(wv[q].w, wv[q].w);
            #pragma unroll
            for (int p = 0; p < 8; p++) {
                const ulonglong2* rr = (const ulonglong2*)&rp[p * CC + 4 * q];
                ulonglong2 ra = rr[0];
                ulonglong2 rb = rr[1];
                acc2[p] = fma2(ra.x, wx, acc2[p]);
                acc2[p] = fma2(ra.y, wy, acc2[p]);
                acc2[p] = fma2(rb.x, wz, acc2[p]);
                acc2[p] = fma2(rb.y, ww2, acc2[p]);
            }
        }
        #pragma unroll
        for (int p = 0; p < 8; p++) {
            float a0, a1; upk2(acc2[p], a0, a1);
            int bt = base + 2 * p;
            g_h1[((size_t)bt * NN + n) * CC + lane]       = ftanh(a0);
            g_h1[((size_t)(bt + 1) * NN + n) * CC + lane] = ftanh(a1);
        }
        __syncwarp();
    }
}

// ================= stage 2: n-major, 2 pipelined chunks of 8 bt =============
__global__ void __launch_bounds__(128, 6) stage2_kernel(const float* __restrict__ bias1,
                              const float* __restrict__ bt1,
                              const float* __restrict__ Wout,
                              const float* __restrict__ bout,
                              float* __restrict__ out) {
    __shared__ float4 sP[4][4][2][CC];   // 16 KB: [warp][pair][half][f]
    int tid = threadIdx.x;
    int lane = tid & 31;
    int w    = tid >> 5;

    float b1 = __ldg(&bias1[lane]), btc = __ldg(&bt1[lane]);
    float wo = __ldg(&Wout[lane]),  bo  = __ldg(&bout[0]);

    int grp = blockIdx.x * 4 + w;
    if (grp >= NG2) return;
    int n  = grp / NTB;
    int tb = grp - n * NTB;
    int bt0v = tb * TB;

    int M   = g_M[0][n];
    int cnt = g_cnt[0][n];
    float inv = g_inv[0][n];
    bool fast = (cnt == KK);

    float wreg = 0.f; int ireg = 0;
    if (lane < M) {
        float2 wi = g_nwi[0][n][lane];
        wreg = wi.x; ireg = __float_as_int(wi.y);
    }
    float wj[KK]; int ij[KK];
    #pragma unroll
    for (int j = 0; j < KK; j++) {
        wj[j] = __shfl_sync(0xffffffffu, wreg, j);
        ij[j] = __shfl_sync(0xffffffffu, ireg, j);
    }

    ull btc2 = pk2(btc, btc);

    #pragma unroll
    for (int ch = 0; ch < 2; ch++) {
        int btc0 = bt0v + ch * CH;
        // ---- phase A: stats for 8 bt ----
        float sw[CH], sq[CH], mxv[CH], mnv[CH];
        #pragma unroll
        for (int u = 0; u < CH; u++) {
            sw[u] = 0.f; sq[u] = 0.f; mxv[u] = -INFINITY; mnv[u] = INFINITY;
        }
        size_t cbase = (size_t)btc0 * NN * CC + lane;
        if (M == KK) {
            #pragma unroll
            for (int j = 0; j < KK; j++) {
                const float* hp = g_h1 + cbase + (size_t)ij[j] * CC;
                float wtj = wj[j];
                bool pos = wtj > 0.f;
                #pragma unroll
                for (int u = 0; u < CH; u++) {
                    float hv = __ldg(hp + (size_t)u * (NN * CC));
                    float t = wtj * hv;
                    sw[u] += t; sq[u] += t * hv;
                    if (pos) { mxv[u] = fmaxf(mxv[u], hv); mnv[u] = fminf(mnv[u], hv); }
                }
            }
        } else {
            for (int j = 0; j < M; j++) {
                float wtj = __shfl_sync(0xffffffffu, wreg, j);
                int   mij = __shfl_sync(0xffffffffu, ireg, j);
                const float* hp = g_h1 + cbase + (size_t)mij * CC;
                bool pos = (j < KK) && (wtj > 0.f);
                #pragma unroll
                for (int u = 0; u < CH; u++) {
                    float hv = __ldg(hp + (size_t)u * (NN * CC));
                    float t = wtj * hv;
                    sw[u] += t; sq[u] += t * hv;
                    if (pos) { mxv[u] = fmaxf(mxv[u], hv); mnv[u] = fminf(mnv[u], hv); }
                }
            }
        }
        #pragma unroll
        for (int u = 0; u < CH; u++) {
            float mean = sw[u] * inv;
            float sd = sqrtf(fmaxf(sq[u] * inv - mean * mean, 0.f) + 1e-5f);
            sw[u] = mean; sq[u] = sd;
        }
        #pragma unroll
        for (int p = 0; p < CH / 2; p++) {
            int u0 = 2 * p, u1 = 2 * p + 1;
            sP[w][p][0][lane] = make_float4(sw[u0], sw[u1], mxv[u0], mxv[u1]);
            sP[w][p][1][lane] = make_float4(mnv[u0], mnv[u1], sq[u0], sq[u1]);
        }
        __syncwarp();

        // ---- phase B: Theta matmul (f32x2), 4 pairs ----
        ull acc[4];
        #pragma unroll
        for (int p = 0; p < 4; p++) acc[p] = pk2(b1, b1);

        if (fast) {
            #pragma unroll 4
            for (int f = 0; f < CC; f++) {
                float4 wv = __ldg(&g_Te3[f * CC + lane]);
                ull wx = pk2(wv.x, wv.x), wy = pk2(wv.y, wv.y);
                ull wz = pk2(wv.z, wv.z), ww2 = pk2(wv.w, wv.w);
                #pragma unroll
                for (int p = 0; p < 4; p++) {
                    ulonglong2 a = *(const ulonglong2*)&sP[w][p][0][f];
                    ulonglong2 b = *(const ulonglong2*)&sP[w][p][1][f];
                    acc[p] = fma2(a.x, wx, acc[p]);
                    acc[p] = fma2(a.y, wy, acc[p]);
                    acc[p] = fma2(b.x, wz, acc[p]);
                    acc[p] = fma2(b.y, ww2, acc[p]);
                }
            }
        } else {
            float s  = log1pf((float)cnt);
            float is = 1.0f / s;
            for (int f = 0; f < CC; f++) {
                float4 a4 = __ldg(&g_TeA[f * CC + lane]);
                float4 b4 = __ldg(&g_TeB[f * CC + lane]);
                float4 c4 = __ldg(&g_TeC[f * CC + lane]);
                float4 wv;
                wv.x = a4.x + s * b4.x + is * c4.x;
                wv.y = a4.y + s * b4.y + is * c4.y;
                wv.z = a4.z + s * b4.z + is * c4.z;
                wv.w = a4.w + s * b4.w + is * c4.w;
                ull wx = pk2(wv.x, wv.x), wy = pk2(wv.y, wv.y);
                ull wz = pk2(wv.z, wv.z), ww2 = pk2(wv.w, wv.w);
                #pragma unroll
                for (int p = 0; p < 4; p++) {
                    ulonglong2 a = *(const ulonglong2*)&sP[w][p][0][f];
                    ulonglong2 b = *(const ulonglong2*)&sP[w][p][1][f];
                    acc[p] = fma2(a.x, wx, acc[p]);
                    acc[p] = fma2(a.y, wy, acc[p]);
                    acc[p] = fma2(b.x, wz, acc[p]);
                    acc[p] = fma2(b.y, ww2, acc[p]);
                }
            }
        }
        __syncwarp();

        // ---- phase C: relu -> tcn1 (f32x2), 4 pairs ----
        float2* rp = (float2*)&sP[w][0][0][0];
        ull racc[4];
        #pragma unroll
        for (int p = 0; p < 4; p++) {
            float a0, a1; upk2(acc[p], a0, a1);
            float r0 = fmaxf(a0, 0.f), r1 = fmaxf(a1, 0.f);
            rp[p * 32 + lane] = make_float2(r0, r1);
            racc[p] = pk2(r0, r1);
        }
        __syncwarp();

        ull acc2[4];
        #pragma unroll
        for (int p = 0; p < 4; p++) acc2[p] = add2(btc2, racc[p]);
        #pragma unroll
        for (int q = 0; q < 8; q++) {
            float4 wq = __ldg(&g_Wt1v[q * CC + lane]);
            ull wx = pk2(wq.x, wq.x), wy = pk2(wq.y, wq.y);
            ull wz = pk2(wq.z, wq.z), ww2 = pk2(wq.w, wq.w);
            #pragma unroll
            for (int p = 0; p < 4; p++) {
                const ulonglong2* rr = (const ulonglong2*)&rp[p * 32 + 4 * q];
                ulonglong2 ra = rr[0];
                ulonglong2 rb = rr[1];
                acc2[p] = fma2(ra.x, wx, acc2[p]);
                acc2[p] = fma2(ra.y, wy, acc2[p]);
                acc2[p] = fma2(rb.x, wz, acc2[p]);
                acc2[p] = fma2(rb.y, ww2, acc2[p]);
            }
        }
        __syncwarp();

        // ---- head ----
        #pragma unroll
        for (int p = 0; p < 4; p++) {
            float t0, t1; upk2(acc2[p], t0, t1);
            float u0 = fmaxf(ftanh(t0), 0.f);
            float u1 = fmaxf(ftanh(t1), 0.f);
            ull pu = pk2(wo * u0, wo * u1);
            #pragma unroll
            for (int off = 16; off > 0; off >>= 1)
                pu = add2(pu, __shfl_xor_sync(0xffffffffu, pu, off));
            if (lane == 0) {
                float s0, s1; upk2(pu, s0, s1);
                out[(size_t)(btc0 + 2 * p)     * NN + n] = s0 + bo;
                out[(size_t)(btc0 + 2 * p + 1) * NN + n] = s1 + bo;
            }
        }
        __syncwarp();
    }
}

extern "C" void kernel_launch(void* const* d_in, const int* in_sizes, int n_in,
                              void* d_out, int out_size) {
    const float* X      = (const float*)d_in[0];
    const float* adj    = (const float*)d_in[1];
    const float* adjm   = (const float*)d_in[2];
    const float* Theta0 = (const float*)d_in[3];
    const float* bias0  = (const float*)d_in[4];
    const float* Wt0    = (const float*)d_in[5];
    const float* bt0    = (const float*)d_in[6];
    const float* Theta1 = (const float*)d_in[7];
    const float* bias1  = (const float*)d_in[8];
    const float* Wt1    = (const float*)d_in[9];
    const float* bt1    = (const float*)d_in[10];
    const float* Wout   = (const float*)d_in[11];
    const float* bout   = (const float*)d_in[12];
    float* out = (float*)d_out;

    setup_kernel<<<880, 256>>>(adj, adjm, Theta1, Wt1, X);
    stage1_kernel<<<250, 256>>>(Theta0, bias0, Wt0, bt0);
    stage2_kernel<<<(NG2 + 3) / 4, 128>>>(bias1, bt1, Wout, bout, out);
}

// round 10
// speedup vs baseline: 3.1493x; 1.0382x over previous
#include <cuda_runtime.h>
#include <math.h>

#define Bb 4
#define Tt 12
#define NN 2000
#define KK 8
#define KMAX 16
#define CC 32
#define NBT (Bb*Tt)          // 48
#define TOT (Bb*Tt*NN)
#define TB  16               // bt per stage2 group
#define CH  8                // stage2 chunk
#define NTB (NBT/TB)         // 3
#define NG2 (NN*NTB)         // 6000 stage2 groups

// ---- scratch (no allocations allowed) ----
__device__ float2 g_nwi[2][NN][KMAX];  // (weight, idx-as-bits)
__device__ int    g_M[2][NN];          // stored entries (<=15)
__device__ int    g_cnt[2][NN];        // true kept count
__device__ float  g_inv[2][NN];        // 1/deg
__device__ float  g_h1[(size_t)TOT * CC];
__device__ float  g_XT[NN * NBT];      // X transposed: [n][bt]
__device__ float4 g_Te3[CC * CC];      // folded Theta1 (s=log1p(8)): [f*32+o]={q0..q3}
__device__ float4 g_TeA[CC * CC];
__device__ float4 g_TeB[CC * CC];
__device__ float4 g_TeC[CC * CC];
__device__ float4 g_Wt1v[8 * CC];      // Wt1: [q*32+o] = Wt1[o][4q..4q+3]

typedef unsigned long long ull;

__device__ __forceinline__ float maskf(float v) {
    if (isnan(v)) v = 6.0f;
    if (isinf(v)) v = 0.0f;
    return fminf(v, 6.0f);
}
__device__ __forceinline__ float ftanh(float x) {
    float e = __expf(2.0f * x);
    return 1.0f - __fdividef(2.0f, e + 1.0f);
}
__device__ __forceinline__ ull pk2(float a, float b) {
    ull r; asm("mov.b64 %0, {%1,%2};" : "=l"(r) : "f"(a), "f"(b)); return r;
}
__device__ __forceinline__ void upk2(ull v, float& a, float& b) {
    asm("mov.b64 {%0,%1}, %2;" : "=f"(a), "=f"(b) : "l"(v));
}
__device__ __forceinline__ ull fma2(ull a, ull b, ull c) {
    ull d; asm("fma.rn.f32x2 %0, %1, %2, %3;" : "=l"(d) : "l"(a), "l"(b), "l"(c)); return d;
}
__device__ __forceinline__ ull add2(ull a, ull b) {
    ull d; asm("add.rn.f32x2 %0, %1, %2;" : "=l"(d) : "l"(a), "l"(b)); return d;
}

#define INS(xx) do { float x_ = (xx); \
    v7 = fmaxf(v7, fminf(v6, x_)); \
    v6 = fmaxf(v6, fminf(v5, x_)); \
    v5 = fmaxf(v5, fminf(v4, x_)); \
    v4 = fmaxf(v4, fminf(v3, x_)); \
    v3 = fmaxf(v3, fminf(v2, x_)); \
    v2 = fmaxf(v2, fminf(v1, x_)); \
    v1 = fmaxf(v1, fminf(v0, x_)); \
    v0 = fmaxf(v0, x_); } while(0)

// ================= setup: topk (blocks 0-499) + prep (500-504) + XT (505-879)
__global__ void __launch_bounds__(256) setup_kernel(const float* __restrict__ adj,
                                                    const float* __restrict__ adjm,
                                                    const float* __restrict__ Theta1,
                                                    const float* __restrict__ Wt1,
                                                    const float* __restrict__ X) {
    __shared__ float2 sCand[8][32][8];    // 16 KB: per-warp per-lane candidate lists
    int b = blockIdx.x;
    int tid = threadIdx.x;
    if (b >= 505) {                       // ---- X transpose ----
        int idx = (b - 505) * 256 + tid;  // idx = n*48 + bt
        g_XT[idx] = X[(idx % NBT) * NN + idx / NBT];
        return;
    }
    if (b >= 500) {                       // ---- weight prep ----
        int idx = (b - 500) * 256 + tid;
        if (idx < CC * CC) {
            int f = idx >> 5, o = idx & 31;
            const float s8  = log1pf(8.0f);
            const float is8 = 1.0f / s8;
            float4 va, vb, vc, ve;
            float *pa=(float*)&va, *pb=(float*)&vb, *pc=(float*)&vc, *pe=(float*)&ve;
            #pragma unroll
            for (int q = 0; q < 4; q++) {
                int src = (q * CC + f) * CC + o;
                float A = Theta1[src];
                float B = Theta1[4*CC*CC + src];
                float C = Theta1[8*CC*CC + src];
                pa[q] = A; pb[q] = B; pc[q] = C;
                pe[q] = A + s8 * B + is8 * C;
            }
            g_TeA[idx] = va; g_TeB[idx] = vb; g_TeC[idx] = vc; g_Te3[idx] = ve;
        } else if (idx < CC * CC + 8 * CC) {
            int i = idx - CC * CC;
            int q = i >> 5, o = i & 31;
            g_Wt1v[i] = ((const float4*)Wt1)[o * 8 + q];
        }
        return;
    }
    // ---- top-K: warp per row (exact tie semantics) ----
    int w = tid >> 5;
    int gw = b * 8 + w;
    int mat = gw / NN;
    int row = gw - mat * NN;
    const float4* src4 = (const float4*)((mat == 0 ? adj : adjm) + (size_t)row * NN);
    int lane = tid & 31;
    unsigned lt = (1u << lane) - 1u;

    // pass 1: vote-free candidate staging (x > CUT), lane-private smem lists
    const float CUT = 0.99f;
    int cnt = 0;
    #pragma unroll
    for (int t = 0; t < 16; t++) {
        int i4 = lane + t * 32;
        float4 f;
        if (i4 < 500) f = __ldg(&src4[i4]);
        else { f.x=f.y=f.z=f.w=-INFINITY; }
        int ib = 4 * i4;
        #pragma unroll
        for (int s = 0; s < 4; s++) {
            float x = (s==0)?f.x:(s==1)?f.y:(s==2)?f.z:f.w;
            if (x > CUT) {
                if (cnt < 8) sCand[w][lane][cnt] = make_float2(x, __int_as_float(ib + s));
                cnt++;
            }
        }
    }
    int total = __reduce_add_sync(0xffffffffu, (unsigned)cnt);
    int maxc  = __reduce_max_sync(0xffffffffu, (unsigned)cnt);
    bool fastp = (total >= KK) && (maxc <= 8);

    float v0=-INFINITY,v1=-INFINITY,v2=-INFINITY,v3=-INFINITY,
          v4=-INFINITY,v5=-INFINITY,v6=-INFINITY,v7=-INFINITY;
    if (fastp) {
        for (int k = 0; k < cnt; k++) INS(sCand[w][lane][k].x);
    } else {
        for (int t = 0; t < 16; t++) {
            int i4 = lane + t * 32;
            if (i4 < 500) {
                float4 f = __ldg(&src4[i4]);
                INS(f.x); INS(f.y); INS(f.z); INS(f.w);
            }
        }
    }

    // 8-round merge -> exact 8th-largest value
    float thr = -INFINITY;
    #pragma unroll
    for (int k = 0; k < 8; k++) {
        float cv = v0; int cl = lane;
        #pragma unroll
        for (int off = 16; off > 0; off >>= 1) {
            float ov = __shfl_xor_sync(0xffffffffu, cv, off);
            int   ol = __shfl_xor_sync(0xffffffffu, cl, off);
            if (ov > cv || (ov == cv && ol < cl)) { cv = ov; cl = ol; }
        }
        if (cl == lane) { v0=v1; v1=v2; v2=v3; v3=v4; v4=v5; v5=v6; v6=v7; v7=-INFINITY; }
        thr = cv;
    }

    bool done = false;
    if (fastp) {
        // staged pass 2: all elements >= thr are candidates (thr > CUT)
        int cgt = 0, ceq = 0;
        float sgt = 0.f;
        for (int k = 0; k < maxc; k++) {
            bool act = k < cnt;
            float2 e = act ? sCand[w][lane][k] : make_float2(-INFINITY, 0.f);
            bool gt = act && (e.x >  thr);
            bool eq = act && (e.x == thr);
            unsigned mgt = __ballot_sync(0xffffffffu, gt);
            unsigned meq = __ballot_sync(0xffffffffu, eq);
            if (gt) {
                int p = cgt + __popc(mgt & lt);
                if (p < 8) g_nwi[mat][row][p] = e;
                sgt += e.x;
            }
            cgt += __popc(mgt);
            if (eq) {
                int p = ceq + __popc(meq & lt);
                if (p < 8) g_nwi[mat][row][8 + p] = e;
            }
            ceq += __popc(meq);
        }
        #pragma unroll
        for (int off = 16; off > 0; off >>= 1)
            sgt += __shfl_xor_sync(0xffffffffu, sgt, off);
        if (cgt + ceq == KK) {     // no ambiguous ties: exact
            if (lane == 0) {
                for (int e2 = 0; e2 < ceq; e2++)
                    g_nwi[mat][row][cgt + e2] = g_nwi[mat][row][8 + e2];
                g_M[mat][row]   = KK;
                g_cnt[mat][row] = KK;
                g_inv[mat][row] = 1.0f / (sgt + (float)ceq * thr);
            }
            done = true;
        }
    }

    if (!done) {     // exact full-row pass 2 (ties / low-candidate rows)
        int cgt = 0, ceq = 0;
        float sgt = 0.f;
        for (int t = 0; t < 16; t++) {
            int i4 = lane + t * 32;
            float4 f;
            if (i4 < 500) f = __ldg(&src4[i4]);
            else { f.x=f.y=f.z=f.w=-INFINITY; }
            bool any = (f.x >= thr) | (f.y >= thr) | (f.z >= thr) | (f.w >= thr);
            if (__ballot_sync(0xffffffffu, any) == 0u) continue;
            int ib = 4 * i4;
            #pragma unroll
            for (int s = 0; s < 4; s++) {
                float x = (s==0)?f.x:(s==1)?f.y:(s==2)?f.z:f.w;
                int   i = ib + s;
                bool gt = x >  thr;
                bool ge = x >= thr;
                unsigned mgt = __ballot_sync(0xffffffffu, gt);
                unsigned mge = __ballot_sync(0xffffffffu, ge);
                unsigned meq = mge & ~mgt;
                if (gt) {
                    int p = cgt + __popc(mgt & lt);
                    g_nwi[mat][row][p] = make_float2(x, __int_as_float(i));
                    sgt += x;
                }
                cgt += __popc(mgt);
                if (meq) {
                    if (ge && !gt) {
                        int p = ceq + __popc(meq & lt);
                        if (p < 8) g_nwi[mat][row][8 + p] = make_float2(x, __int_as_float(i));
                    }
                    ceq += __popc(meq);
                }
            }
        }
        #pragma unroll
        for (int off = 16; off > 0; off >>= 1)
            sgt += __shfl_xor_sync(0xffffffffu, sgt, off);

        if (lane == 0) {
            int cnt2 = cgt + ceq;
            int eq_stored = ceq < 8 ? ceq : 8;
            int M = cgt + eq_stored;
            for (int e2 = 0; e2 < eq_stored; e2++)
                g_nwi[mat][row][cgt + e2] = g_nwi[mat][row][8 + e2];
            g_M[mat][row]   = M;
            g_cnt[mat][row] = cnt2;
            g_inv[mat][row] = 1.0f / (sgt + (float)ceq * thr);
        }
    }
}
#undef INS

// ================= stage 1: n-major, warp = n x 48 bt, scalar stats =========
__global__ void __launch_bounds__(256) stage1_kernel(const float* __restrict__ Theta0,
                              const float* __restrict__ bias0,
                              const float* __restrict__ Wt0,
                              const float* __restrict__ bt0) {
    __shared__ float4 sStat[8][NBT];
    __shared__ float2 sR[8][8 * CC];
    int tid = threadIdx.x;
    int lane = tid & 31;
    int w    = tid >> 5;
    int n = blockIdx.x * 8 + w;

    float b0  = __ldg(&bias0[lane]), btc = __ldg(&bt0[lane]);
    ull t0m = pk2(__ldg(&Theta0[lane]),        __ldg(&Theta0[lane]));
    ull t0x = pk2(__ldg(&Theta0[CC+lane]),     __ldg(&Theta0[CC+lane]));
    ull t0n = pk2(__ldg(&Theta0[2*CC+lane]),   __ldg(&Theta0[2*CC+lane]));
    ull t0s = pk2(__ldg(&Theta0[3*CC+lane]),   __ldg(&Theta0[3*CC+lane]));
    float4 wv[8];
    #pragma unroll
    for (int q = 0; q < 8; q++) wv[q] = __ldg(&((const float4*)Wt0)[lane * 8 + q]);

    int M = g_M[1][n];
    float inv = g_inv[1][n];
    float wreg = 0.f; int ireg = 0;
    if (lane < M) {
        float2 wi = g_nwi[1][n][lane];
        wreg = wi.x; ireg = __float_as_int(wi.y);
    }

    float sw0=0.f, sq0=0.f, mx0=-INFINITY, mn0=INFINITY;
    float sw1=0.f, sq1=0.f, mx1=-INFINITY, mn1=INFINITY;
    if (M == KK) {
        #pragma unroll
        for (int j = 0; j < KK; j++) {
            float wtj = __shfl_sync(0xffffffffu, wreg, j);
            int   mij = __shfl_sync(0xffffffffu, ireg, j);
            const float* xp = g_XT + mij * NBT;
            float x0 = __ldg(xp + lane);
            float x1 = (lane < 16) ? __ldg(xp + 32 + lane) : 0.f;
            float t0 = wtj * x0, t1 = wtj * x1;
            sw0 += t0; sq0 += t0 * x0;
            sw1 += t1; sq1 += t1 * x1;
            if (wtj > 0.f) {
                mx0 = fmaxf(mx0, x0); mn0 = fminf(mn0, x0);
                mx1 = fmaxf(mx1, x1); mn1 = fminf(mn1, x1);
            }
        }
    } else {
        for (int j = 0; j < M; j++) {
            float wtj = __shfl_sync(0xffffffffu, wreg, j);
            int   mij = __shfl_sync(0xffffffffu, ireg, j);
            const float* xp = g_XT + mij * NBT;
            float x0 = __ldg(xp + lane);
            float x1 = (lane < 16) ? __ldg(xp + 32 + lane) : 0.f;
            float t0 = wtj * x0, t1 = wtj * x1;
            sw0 += t0; sq0 += t0 * x0;
            sw1 += t1; sq1 += t1 * x1;
            if (j < KK && wtj > 0.f) {
                mx0 = fmaxf(mx0, x0); mn0 = fminf(mn0, x0);
                mx1 = fmaxf(mx1, x1); mn1 = fminf(mn1, x1);
            }
        }
    }
    {
        float mean = sw0 * inv;
        float sd = sqrtf(fmaxf(sq0 * inv - mean * mean, 0.f) + 1e-5f);
        sStat[w][lane] = make_float4(maskf(mean), maskf(mx0), maskf(mn0), maskf(sd));
    }
    if (lane < 16) {
        float mean = sw1 * inv;
        float sd = sqrtf(fmaxf(sq1 * inv - mean * mean, 0.f) + 1e-5f);
        sStat[w][32 + lane] = make_float4(maskf(mean), maskf(mx1), maskf(mn1), maskf(sd));
    }
    __syncwarp();

    ull b02 = pk2(b0, b0), btc2 = pk2(btc, btc);
    #pragma unroll
    for (int s = 0; s < NTB; s++) {
        int base = s * TB;
        float2* rp = &sR[w][0];
        ull racc[8];
        #pragma unroll
        for (int p = 0; p < 8; p++) {
            float4 A = sStat[w][base + 2 * p];
            float4 B = sStat[w][base + 2 * p + 1];
            ull o2 = b02;
            o2 = fma2(pk2(A.x, B.x), t0m, o2);
            o2 = fma2(pk2(A.y, B.y), t0x, o2);
            o2 = fma2(pk2(A.z, B.z), t0n, o2);
            o2 = fma2(pk2(A.w, B.w), t0s, o2);
            float f0, f1; upk2(o2, f0, f1);
            rp[p * CC + lane] = make_float2(f0, f1);
            racc[p] = o2;
        }
        __syncwarp();
        ull acc2[8];
        #pragma unroll
        for (int p = 0; p < 8; p++) acc2[p] = add2(btc2, racc[p]);
        #pragma unroll
        for (int q = 0; q < 8; q++) {
            ull wx = pk2(wv[q].x, wv[q].x), wy = pk2(wv[q].y, wv[q].y);
            ull wz = pk2(wv[q].z, wv[q].z), ww2 = pk2(wv[q].w, wv[q].w);
            #pragma unroll
            for (int p = 0; p < 8; p++) {
                const ulonglong2* rr = (const ulonglong2*)&rp[p * CC + 4 * q];
                ulonglong2 ra = rr[0];
                ulonglong2 rb = rr[1];
                acc2[p] = fma2(ra.x, wx, acc2[p]);
                acc2[p] = fma2(ra.y, wy, acc2[p]);
                acc2[p] = fma2(rb.x, wz, acc2[p]);
                acc2[p] = fma2(rb.y, ww2, acc2[p]);
            }
        }
        #pragma unroll
        for (int p = 0; p < 8; p++) {
            float a0, a1; upk2(acc2[p], a0, a1);
            int bt = base + 2 * p;
            g_h1[((size_t)bt * NN + n) * CC + lane]       = ftanh(a0);
            g_h1[((size_t)(bt + 1) * NN + n) * CC + lane] = ftanh(a1);
        }
        __syncwarp();
    }
}

// ================= stage 2: n-major, 2 pipelined chunks of 8 bt =============
__global__ void __launch_bounds__(128, 6) stage2_kernel(const float* __restrict__ bias1,
                              const float* __restrict__ bt1,
                              const float* __restrict__ Wout,
                              const float* __restrict__ bout,
                              float* __restrict__ out) {
    __shared__ float4 sP[4][4][2][CC];   // 16 KB
    int tid = threadIdx.x;
    int lane = tid & 31;
    int w    = tid >> 5;

    float b1 = __ldg(&bias1[lane]), btc = __ldg(&bt1[lane]);
    float wo = __ldg(&Wout[lane]),  bo  = __ldg(&bout[0]);

    int grp = blockIdx.x * 4 + w;
    if (grp >= NG2) return;
    int n  = grp / NTB;
    int tb = grp - n * NTB;
    int bt0v = tb * TB;

    int M   = g_M[0][n];
    int cnt = g_cnt[0][n];
    float inv = g_inv[0][n];
    bool fast = (cnt == KK);

    float wreg = 0.f; int ireg = 0;
    if (lane < M) {
        float2 wi = g_nwi[0][n][lane];
        wreg = wi.x; ireg = __float_as_int(wi.y);
    }
    float wj[KK]; int ij[KK];
    #pragma unroll
    for (int j = 0; j < KK; j++) {
        wj[j] = __shfl_sync(0xffffffffu, wreg, j);
        ij[j] = __shfl_sync(0xffffffffu, ireg, j);
    }

    ull btc2 = pk2(btc, btc);

    #pragma unroll
    for (int ch = 0; ch < 2; ch++) {
        int btc0 = bt0v + ch * CH;
        float sw[CH], sq[CH], mxv[CH], mnv[CH];
        #pragma unroll
        for (int u = 0; u < CH; u++) {
            sw[u] = 0.f; sq[u] = 0.f; mxv[u] = -INFINITY; mnv[u] = INFINITY;
        }
        size_t cbase = (size_t)btc0 * NN * CC + lane;
        if (M == KK) {
            #pragma unroll
            for (int j = 0; j < KK; j++) {
                const float* hp = g_h1 + cbase + (size_t)ij[j] * CC;
                float wtj = wj[j];
                bool pos = wtj > 0.f;
                #pragma unroll
                for (int u = 0; u < CH; u++) {
                    float hv = __ldg(hp + (size_t)u * (NN * CC));
                    float t = wtj * hv;
                    sw[u] += t; sq[u] += t * hv;
                    if (pos) { mxv[u] = fmaxf(mxv[u], hv); mnv[u] = fminf(mnv[u], hv); }
                }
            }
        } else {
            for (int j = 0; j < M; j++) {
                float wtj = __shfl_sync(0xffffffffu, wreg, j);
                int   mij = __shfl_sync(0xffffffffu, ireg, j);
                const float* hp = g_h1 + cbase + (size_t)mij * CC;
                bool pos = (j < KK) && (wtj > 0.f);
                #pragma unroll
                for (int u = 0; u < CH; u++) {
                    float hv = __ldg(hp + (size_t)u * (NN * CC));
                    float t = wtj * hv;
                    sw[u] += t; sq[u] += t * hv;
                    if (pos) { mxv[u] = fmaxf(mxv[u], hv); mnv[u] = fminf(mnv[u], hv); }
                }
            }
        }
        #pragma unroll
        for (int u = 0; u < CH; u++) {
            float mean = sw[u] * inv;
            float sd = sqrtf(fmaxf(sq[u] * inv - mean * mean, 0.f) + 1e-5f);
            sw[u] = mean; sq[u] = sd;
        }
        #pragma unroll
        for (int p = 0; p < CH / 2; p++) {
            int u0 = 2 * p, u1 = 2 * p + 1;
            sP[w][p][0][lane] = make_float4(sw[u0], sw[u1], mxv[u0], mxv[u1]);
            sP[w][p][1][lane] = make_float4(mnv[u0], mnv[u1], sq[u0], sq[u1]);
        }
        __syncwarp();

        ull acc[4];
        #pragma unroll
        for (int p = 0; p < 4; p++) acc[p] = pk2(b1, b1);

        if (fast) {
            #pragma unroll 4
            for (int f = 0; f < CC; f++) {
                float4 wvv = __ldg(&g_Te3[f * CC + lane]);
                ull wx = pk2(wvv.x, wvv.x), wy = pk2(wvv.y, wvv.y);
                ull wz = pk2(wvv.z, wvv.z), ww2 = pk2(wvv.w, wvv.w);
                #pragma unroll
                for (int p = 0; p < 4; p++) {
                    ulonglong2 a = *(const ulonglong2*)&sP[w][p][0][f];
                    ulonglong2 bb = *(const ulonglong2*)&sP[w][p][1][f];
                    acc[p] = fma2(a.x, wx, acc[p]);
                    acc[p] = fma2(a.y, wy, acc[p]);
                    acc[p] = fma2(bb.x, wz, acc[p]);
                    acc[p] = fma2(bb.y, ww2, acc[p]);
                }
            }
        } else {
            float s  = log1pf((float)cnt);
            float is = 1.0f / s;
            for (int f = 0; f < CC; f++) {
                float4 a4 = __ldg(&g_TeA[f * CC + lane]);
                float4 b4 = __ldg(&g_TeB[f * CC + lane]);
                float4 c4 = __ldg(&g_TeC[f * CC + lane]);
                float4 wvv;
                wvv.x = a4.x + s * b4.x + is * c4.x;
                wvv.y = a4.y + s * b4.y + is * c4.y;
                wvv.z = a4.z + s * b4.z + is * c4.z;
                wvv.w = a4.w + s * b4.w + is * c4.w;
                ull wx = pk2(wvv.x, wvv.x), wy = pk2(wvv.y, wvv.y);
                ull wz = pk2(wvv.z, wvv.z), ww2 = pk2(wvv.w, wvv.w);
                #pragma unroll
                for (int p = 0; p < 4; p++) {
                    ulonglong2 a = *(const ulonglong2*)&sP[w][p][0][f];
                    ulonglong2 bb = *(const ulonglong2*)&sP[w][p][1][f];
                    acc[p] = fma2(a.x, wx, acc[p]);
                    acc[p] = fma2(a.y, wy, acc[p]);
                    acc[p] = fma2(bb.x, wz, acc[p]);
                    acc[p] = fma2(bb.y, ww2, acc[p]);
                }
            }
        }
        __syncwarp();

        float2* rp = (float2*)&sP[w][0][0][0];
        ull racc[4];
        #pragma unroll
        for (int p = 0; p < 4; p++) {
            float a0, a1; upk2(acc[p], a0, a1);
            float r0 = fmaxf(a0, 0.f), r1 = fmaxf(a1, 0.f);
            rp[p * 32 + lane] = make_float2(r0, r1);
            racc[p] = pk2(r0, r1);
        }
        __syncwarp();

        ull acc2[4];
        #pragma unroll
        for (int p = 0; p < 4; p++) acc2[p] = add2(btc2, racc[p]);
        #pragma unroll
        for (int q = 0; q < 8; q++) {
            float4 wq = __ldg(&g_Wt1v[q * CC + lane]);
            ull wx = pk2(wq.x, wq.x), wy = pk2(wq.y, wq.y);
            ull wz = pk2(wq.z, wq.z), ww2 = pk2(wq.w, wq.w);
            #pragma unroll
            for (int p = 0; p < 4; p++) {
                const ulonglong2* rr = (const ulonglong2*)&rp[p * 32 + 4 * q];
                ulonglong2 ra = rr[0];
                ulonglong2 rb = rr[1];
                acc2[p] = fma2(ra.x, wx, acc2[p]);
                acc2[p] = fma2(ra.y, wy, acc2[p]);
                acc2[p] = fma2(rb.x, wz, acc2[p]);
                acc2[p] = fma2(rb.y, ww2, acc2[p]);
            }
        }
        __syncwarp();

        #pragma unroll
        for (int p = 0; p < 4; p++) {
            float t0, t1; upk2(acc2[p], t0, t1);
            float u0 = fmaxf(ftanh(t0), 0.f);
            float u1 = fmaxf(ftanh(t1), 0.f);
            ull pu = pk2(wo * u0, wo * u1);
            #pragma unroll
            for (int off = 16; off > 0; off >>= 1)
                pu = add2(pu, __shfl_xor_sync(0xffffffffu, pu, off));
            if (lane == 0) {
                float s0, s1; upk2(pu, s0, s1);
                out[(size_t)(btc0 + 2 * p)     * NN + n] = s0 + bo;
                out[(size_t)(btc0 + 2 * p + 1) * NN + n] = s1 + bo;
            }
        }
        __syncwarp();
    }
}

extern "C" void kernel_launch(void* const* d_in, const int* in_sizes, int n_in,
                              void* d_out, int out_size) {
    const float* X      = (const float*)d_in[0];
    const float* adj    = (const float*)d_in[1];
    const float* adjm   = (const float*)d_in[2];
    const float* Theta0 = (const float*)d_in[3];
    const float* bias0  = (const float*)d_in[4];
    const float* Wt0    = (const float*)d_in[5];
    const float* bt0    = (const float*)d_in[6];
    const float* Theta1 = (const float*)d_in[7];
    const float* bias1  = (const float*)d_in[8];
    const float* Wt1    = (const float*)d_in[9];
    const float* bt1    = (const float*)d_in[10];
    const float* Wout   = (const float*)d_in[11];
    const float* bout   = (const float*)d_in[12];
    float* out = (float*)d_out;

    setup_kernel<<<880, 256>>>(adj, adjm, Theta1, Wt1, X);
    stage1_kernel<<<250, 256>>>(Theta0, bias0, Wt0, bt0);
    stage2_kernel<<<(NG2 + 3) / 4, 128>>>(bias1, bt1, Wout, bout, out);
}